// round 10
// baseline (speedup 1.0000x reference)
#include <cuda_runtime.h>
#include <cuda_bf16.h>
#include <cstdint>
#include <cstddef>

#define Hh 512
#define Aa 16
#define Bb 256
#define Tt 512
#define BT (Bb*Tt)          // 131072 rows
#define H3 1536

// ---------------- device-global scratch (no allocation allowed) -------------
__device__ float g_buf0[(size_t)BT*Hh];             // 256 MB
__device__ float g_gi[(size_t)BT*H3];               // 768 MB
__device__ __nv_bfloat16 g_Ah[(size_t)BT*Hh];       // 128 MB
__device__ __nv_bfloat16 g_Al[(size_t)BT*Hh];       // 128 MB
#define OFF_INW 0
#define OFF_WIH (3*Hh*Hh)
#define OFF_AM1 (3*Hh*Hh + H3*Hh)
#define W_TOTAL (3*Hh*Hh + H3*Hh + Hh*Hh)
__device__ __nv_bfloat16 g_Wh[W_TOTAL];
__device__ __nv_bfloat16 g_Wl[W_TOTAL];
__device__ __nv_bfloat16 g_hbh[Bb*Hh];              // bf16 hi initial hidden
__device__ __nv_bfloat16 g_hbl[Bb*Hh];              // bf16 lo initial hidden
__device__ unsigned g_bar[4*Tt];                    // per-(btile,step) counters

// ---------------- helpers ----------------------------------------------------
__device__ __forceinline__ float sigmoidf_(float x){
    return 1.f / (1.f + __expf(-x));
}
__device__ __forceinline__ float tanhf_fast(float x){
    float e = __expf(2.f*x);
    return 1.f - 2.f/(e + 1.f);
}
__device__ __forceinline__ uint32_t smem_u32(const void* p){
    uint32_t a;
    asm("{ .reg .u64 t; cvta.to.shared.u64 t, %1; cvt.u32.u64 %0, t; }"
        : "=r"(a) : "l"(p));
    return a;
}
__device__ __forceinline__ uint32_t pack_bf2(__nv_bfloat16 a, __nv_bfloat16 b){
    __nv_bfloat162 p = __halves2bfloat162(a, b);
    return *reinterpret_cast<uint32_t*>(&p);
}
__device__ __forceinline__ void split_bf(float x, __nv_bfloat16& h, __nv_bfloat16& l){
    h = __float2bfloat16(x);
    l = __float2bfloat16(x - __bfloat162float(h));
}

// ---------------- init: clear barriers + split hidden -> bf16 hi/lo ---------
__global__ void __launch_bounds__(256) init_misc_kernel(const float* __restrict__ hidden)
{
    int idx = blockIdx.x*256 + threadIdx.x;     // 32768 threads
    if (idx < 4*Tt) g_bar[idx] = 0u;
    float4 v = __ldg(reinterpret_cast<const float4*>(hidden) + idx);
    __nv_bfloat16 h0,h1,h2,h3,l0,l1,l2,l3;
    split_bf(v.x,h0,l0); split_bf(v.y,h1,l1); split_bf(v.z,h2,l2); split_bf(v.w,h3,l3);
    reinterpret_cast<uint2*>(g_hbh)[idx] = make_uint2(pack_bf2(h0,h1), pack_bf2(h2,h3));
    reinterpret_cast<uint2*>(g_hbl)[idx] = make_uint2(pack_bf2(l0,l1), pack_bf2(l2,l3));
}

// ---------------- merged weight split (in_w | wih | am1_w) ------------------
#define CW_N0 (3*Hh*Hh/4)
#define CW_N1 (CW_N0 + H3*Hh/4)
#define CW_TOT (W_TOTAL/4)
__global__ void __launch_bounds__(256) conv_w3_kernel(
    const float* __restrict__ w0, const float* __restrict__ w1,
    const float* __restrict__ w2)
{
    int idx = blockIdx.x*256 + threadIdx.x;
    if (idx >= CW_TOT) return;
    const float* src; int s;
    if (idx < CW_N0){ src = w0; s = idx; }
    else if (idx < CW_N1){ src = w1; s = idx - CW_N0; }
    else { src = w2; s = idx - CW_N1; }
    float4 v = __ldg(reinterpret_cast<const float4*>(src) + s);
    __nv_bfloat16 h0,h1,h2,h3,l0,l1,l2,l3;
    split_bf(v.x,h0,l0); split_bf(v.y,h1,l1); split_bf(v.z,h2,l2); split_bf(v.w,h3,l3);
    reinterpret_cast<uint2*>(g_Wh)[idx] = make_uint2(pack_bf2(h0,h1), pack_bf2(h2,h3));
    reinterpret_cast<uint2*>(g_Wl)[idx] = make_uint2(pack_bf2(l0,l1), pack_bf2(l2,l3));
}

// ---------------- split fp32 -> bf16 hi/lo (obs) ----------------------------
__global__ void __launch_bounds__(256) conv_split_kernel(
    const float* __restrict__ x, __nv_bfloat16* __restrict__ hi,
    __nv_bfloat16* __restrict__ lo, size_t n4)
{
    size_t i = (size_t)blockIdx.x*256 + threadIdx.x;
    size_t stride = (size_t)gridDim.x*256;
    for (; i < n4; i += stride){
        float4 v = __ldg(reinterpret_cast<const float4*>(x) + i);
        __nv_bfloat16 h0,h1,h2,h3,l0,l1,l2,l3;
        split_bf(v.x,h0,l0); split_bf(v.y,h1,l1); split_bf(v.z,h2,l2); split_bf(v.w,h3,l3);
        reinterpret_cast<uint2*>(hi)[i] = make_uint2(pack_bf2(h0,h1), pack_bf2(h2,h3));
        reinterpret_cast<uint2*>(lo)[i] = make_uint2(pack_bf2(l0,l1), pack_bf2(l2,l3));
    }
}

// ---------------- bf16 tensor-core GEMM: C = A @ B^T + bias -----------------
#define STG_B 65536
#define GEMM_SMEM3 (3*STG_B + 512)

__global__ void __launch_bounds__(256) gemm_bf16_bias(
    const __nv_bfloat16* __restrict__ Ah, const __nv_bfloat16* __restrict__ Al,
    const __nv_bfloat16* __restrict__ Bh, const __nv_bfloat16* __restrict__ Bl,
    const float* __restrict__ bias, float* __restrict__ C, int N, int K)
{
    extern __shared__ char gsm[];
    uint32_t sb = smem_u32(gsm);
    float* biasS = reinterpret_cast<float*>(gsm + 3*STG_B);

    int tid = threadIdx.x;
    int lane = tid & 31, wid = tid >> 5;
    int wm = wid & 1, wn = wid >> 1;
    int n0 = blockIdx.x * 128, m0 = blockIdx.y * 128;

    if (tid < 128) biasS[tid] = bias[n0 + tid];

    float acc[4][4][4];
#pragma unroll
    for (int mt=0; mt<4; mt++)
#pragma unroll
        for (int nt=0; nt<4; nt++)
#pragma unroll
            for (int q=0; q<4; q++) acc[mt][nt][q] = 0.f;

    const int tot = K >> 6;
    const __nv_bfloat16* srcs[4] = {Ah, Al, Bh, Bl};

    auto issue = [&](int c){
        uint32_t base = sb + (uint32_t)(c % 3)*STG_B;
        int kk = c << 6;
#pragma unroll
        for (int tI = 0; tI < 4; tI++){
            const __nv_bfloat16* sp = srcs[tI];
            int rb = (tI < 2) ? m0 : n0;
            uint32_t tBase = base + tI*16384;
#pragma unroll
            for (int i = 0; i < 4; i++){
                int idx = i*256 + tid;
                int r = idx >> 3, cc = idx & 7;
                uint32_t so = (uint32_t)(r*128 + cc*16);
                so ^= (so >> 3) & 0x70;
                const void* g = sp + (size_t)(rb + r)*K + kk + cc*8;
                asm volatile("cp.async.cg.shared.global [%0], [%1], 16;"
                             :: "r"(tBase + so), "l"(g));
            }
        }
        asm volatile("cp.async.commit_group;");
    };

    issue(0);
    if (tot > 1) issue(1);

    for (int c = 0; c < tot; c++){
        if (c + 2 < tot){
            issue(c + 2);
            asm volatile("cp.async.wait_group 2;");
        } else if (c + 1 < tot){
            asm volatile("cp.async.wait_group 1;");
        } else {
            asm volatile("cp.async.wait_group 0;");
        }
        __syncthreads();
        uint32_t base  = sb + (uint32_t)(c % 3)*STG_B;
        uint32_t aHB = base, aLB = base + 16384;
        uint32_t bHB = base + 32768, bLB = base + 49152;

        int mat = lane >> 3;
        int rowp = ((mat & 2) << 2) + (lane & 7);
        int khalf = (mat & 1) << 4;

#pragma unroll
        for (int ks = 0; ks < 4; ks++){
            uint32_t ah[4][4], al[4][4], bh[4][2], bl[4][2];
#pragma unroll
            for (int mt = 0; mt < 4; mt++){
                uint32_t off = (uint32_t)((wm*64 + mt*16 + (lane & 15))*128
                              + ks*32 + ((lane >> 4) << 4));
                off ^= (off >> 3) & 0x70;
                asm volatile("ldmatrix.sync.aligned.m8n8.x4.shared.b16 "
                    "{%0,%1,%2,%3}, [%4];"
                    : "=r"(ah[mt][0]),"=r"(ah[mt][1]),"=r"(ah[mt][2]),"=r"(ah[mt][3])
                    : "r"(aHB + off));
                asm volatile("ldmatrix.sync.aligned.m8n8.x4.shared.b16 "
                    "{%0,%1,%2,%3}, [%4];"
                    : "=r"(al[mt][0]),"=r"(al[mt][1]),"=r"(al[mt][2]),"=r"(al[mt][3])
                    : "r"(aLB + off));
            }
#pragma unroll
            for (int ntp = 0; ntp < 2; ntp++){
                uint32_t off = (uint32_t)((wn*32 + ntp*16 + rowp)*128
                              + ks*32 + khalf);
                off ^= (off >> 3) & 0x70;
                asm volatile("ldmatrix.sync.aligned.m8n8.x4.shared.b16 "
                    "{%0,%1,%2,%3}, [%4];"
                    : "=r"(bh[ntp*2][0]),"=r"(bh[ntp*2][1]),
                      "=r"(bh[ntp*2+1][0]),"=r"(bh[ntp*2+1][1])
                    : "r"(bHB + off));
                asm volatile("ldmatrix.sync.aligned.m8n8.x4.shared.b16 "
                    "{%0,%1,%2,%3}, [%4];"
                    : "=r"(bl[ntp*2][0]),"=r"(bl[ntp*2][1]),
                      "=r"(bl[ntp*2+1][0]),"=r"(bl[ntp*2+1][1])
                    : "r"(bLB + off));
            }
#define MMA16(AV, BV, mt, nt) \
    asm volatile("mma.sync.aligned.m16n8k16.row.col.f32.bf16.bf16.f32 " \
        "{%0,%1,%2,%3}, {%4,%5,%6,%7}, {%8,%9}, {%0,%1,%2,%3};" \
        : "+f"(acc[mt][nt][0]), "+f"(acc[mt][nt][1]), \
          "+f"(acc[mt][nt][2]), "+f"(acc[mt][nt][3]) \
        : "r"(AV[mt][0]),"r"(AV[mt][1]),"r"(AV[mt][2]),"r"(AV[mt][3]), \
          "r"(BV[nt][0]),"r"(BV[nt][1]));
#pragma unroll
            for (int mt = 0; mt < 4; mt++)
#pragma unroll
                for (int nt = 0; nt < 4; nt++){
                    MMA16(ah, bh, mt, nt);
                    MMA16(al, bh, mt, nt);
                    MMA16(ah, bl, mt, nt);
                }
#undef MMA16
        }
        __syncthreads();
    }

#pragma unroll
    for (int mt = 0; mt < 4; mt++){
        int r0 = m0 + wm*64 + mt*16 + (lane >> 2);
#pragma unroll
        for (int nt = 0; nt < 4; nt++){
            int nl = wn*32 + nt*8 + (lane & 3)*2;
            float bx = biasS[nl], by = biasS[nl+1];
            float2 v0 = make_float2(acc[mt][nt][0] + bx, acc[mt][nt][1] + by);
            float2 v1 = make_float2(acc[mt][nt][2] + bx, acc[mt][nt][3] + by);
            *reinterpret_cast<float2*>(&C[(size_t)r0*N + n0 + nl]) = v0;
            *reinterpret_cast<float2*>(&C[(size_t)(r0+8)*N + n0 + nl]) = v1;
        }
    }
}

// ---------------- LayerNorm + ReLU in place (fp32) --------------------------
__global__ void __launch_bounds__(128) ln_relu_kernel(
    float* __restrict__ X, const float* __restrict__ gamma,
    const float* __restrict__ beta)
{
    size_t row = blockIdx.x;
    float* x = X + row*Hh;
    int tid = threadIdx.x;
    float4 v = *reinterpret_cast<float4*>(&x[tid*4]);
    float s = v.x+v.y+v.z+v.w;
    float q = v.x*v.x + v.y*v.y + v.z*v.z + v.w*v.w;
#pragma unroll
    for (int o=16;o>0;o>>=1){
        s += __shfl_xor_sync(0xffffffffu, s, o);
        q += __shfl_xor_sync(0xffffffffu, q, o);
    }
    __shared__ float ss[4], qq[4];
    if ((tid & 31) == 0){ ss[tid>>5] = s; qq[tid>>5] = q; }
    __syncthreads();
    s = ss[0]+ss[1]+ss[2]+ss[3];
    q = qq[0]+qq[1]+qq[2]+qq[3];
    float mu  = s * (1.f/Hh);
    float var = q * (1.f/Hh) - mu*mu;
    float inv = rsqrtf(var + 1e-5f);
    float4 g4 = *reinterpret_cast<const float4*>(&gamma[tid*4]);
    float4 b4 = *reinterpret_cast<const float4*>(&beta[tid*4]);
    v.x = fmaxf((v.x-mu)*inv*g4.x + b4.x, 0.f);
    v.y = fmaxf((v.y-mu)*inv*g4.y + b4.y, 0.f);
    v.z = fmaxf((v.z-mu)*inv*g4.z + b4.z, 0.f);
    v.w = fmaxf((v.w-mu)*inv*g4.w + b4.w, 0.f);
    *reinterpret_cast<float4*>(&x[tid*4]) = v;
}

// ---------------- LayerNorm + ReLU -> bf16 hi/lo split ----------------------
__global__ void __launch_bounds__(128) ln_relu_conv_kernel(
    const float* __restrict__ X, const float* __restrict__ gamma,
    const float* __restrict__ beta,
    __nv_bfloat16* __restrict__ oh, __nv_bfloat16* __restrict__ ol)
{
    size_t row = blockIdx.x;
    const float* x = X + row*Hh;
    int tid = threadIdx.x;
    float4 v = *reinterpret_cast<const float4*>(&x[tid*4]);
    float s = v.x+v.y+v.z+v.w;
    float q = v.x*v.x + v.y*v.y + v.z*v.z + v.w*v.w;
#pragma unroll
    for (int o=16;o>0;o>>=1){
        s += __shfl_xor_sync(0xffffffffu, s, o);
        q += __shfl_xor_sync(0xffffffffu, q, o);
    }
    __shared__ float ss[4], qq[4];
    if ((tid & 31) == 0){ ss[tid>>5] = s; qq[tid>>5] = q; }
    __syncthreads();
    s = ss[0]+ss[1]+ss[2]+ss[3];
    q = qq[0]+qq[1]+qq[2]+qq[3];
    float mu  = s * (1.f/Hh);
    float var = q * (1.f/Hh) - mu*mu;
    float inv = rsqrtf(var + 1e-5f);
    float4 g4 = *reinterpret_cast<const float4*>(&gamma[tid*4]);
    float4 b4 = *reinterpret_cast<const float4*>(&beta[tid*4]);
    v.x = fmaxf((v.x-mu)*inv*g4.x + b4.x, 0.f);
    v.y = fmaxf((v.y-mu)*inv*g4.y + b4.y, 0.f);
    v.z = fmaxf((v.z-mu)*inv*g4.z + b4.z, 0.f);
    v.w = fmaxf((v.w-mu)*inv*g4.w + b4.w, 0.f);
    __nv_bfloat16 h0,h1,h2,h3,l0,l1,l2,l3;
    split_bf(v.x,h0,l0); split_bf(v.y,h1,l1); split_bf(v.z,h2,l2); split_bf(v.w,h3,l3);
    size_t i = row*128 + tid;
    reinterpret_cast<uint2*>(oh)[i] = make_uint2(pack_bf2(h0,h1), pack_bf2(h2,h3));
    reinterpret_cast<uint2*>(ol)[i] = make_uint2(pack_bf2(l0,l1), pack_bf2(l2,l3));
}

// ---------------- persistent GRU scan: split-bf16 mma ------------------------
// h state lives directly in the outs arrays (oh/ol): step t reads row
// b*Tt+(t-1) (or the initial-hidden buffer at t=0) and writes row b*Tt+t.
#define SW_WH 0
#define SW_WL 49152
#define SW_AH 98304
#define SW_AL 163840
#define SW_MS 229376
#define SC_SMEM (229376 + 256)

__global__ void __launch_bounds__(256) gru_scan_mma(
    const float* __restrict__ gi,        // [B*T][3H] (includes bih)
    const float* __restrict__ whh,       // [3H][H]
    const float* __restrict__ bhh,       // [3H]
    const unsigned* __restrict__ dones,  // [B][T] 4-byte words
    const float* __restrict__ hidden,    // [B][H] fp32 h_0
    __nv_bfloat16* __restrict__ oh,      // [B][T][H] bf16 hi (state + outs)
    __nv_bfloat16* __restrict__ ol,
    float* __restrict__ hfin)            // [B][H] fp32 -> d_out head
{
    extern __shared__ char ssm[];
    uint32_t sb = smem_u32(ssm);
    float* Ms = reinterpret_cast<float*>(ssm + SW_MS);

    int tid = threadIdx.x;
    int lane = tid & 31, wid = tid >> 5;
    int mt = wid & 3, cb = wid >> 2;
    int bt = blockIdx.x >> 5, jt = blockIdx.x & 31;
    int b0 = bt*64, j0 = jt*16;

    // load Whh slice (48 rows x 512 k) into smem as bf16 hi/lo, swizzled
    for (int idx = tid; idx < 48*512; idx += 256){
        int rr = idx >> 9;          // 0..47 = g*16 + jc
        int k  = idx & 511;
        int g = rr >> 4, jc = rr & 15;
        int cbw = jc >> 3, rw = jc & 7;
        float w = whh[(size_t)(g*Hh + j0 + jc)*Hh + k];
        __nv_bfloat16 h, l; split_bf(w, h, l);
        int kc = k >> 6, kk = k & 63;
        uint32_t off = (uint32_t)((g*2+cbw)*8192 + kc*1024 + rw*128 + kk*2);
        uint32_t sw = off ^ ((off >> 3) & 0x70);
        *reinterpret_cast<__nv_bfloat16*>(ssm + SW_WH + sw) = h;
        *reinterpret_cast<__nv_bfloat16*>(ssm + SW_WL + sw) = l;
    }

    int r0l = lane >> 2;                 // 0..7
    int mr0 = mt*16 + r0l, mr1 = mr0 + 8;
    int gb0 = b0 + mr0,   gb1 = b0 + mr1;
    int jcol = j0 + cb*8 + (lane & 3)*2;

    float2 bhr = *reinterpret_cast<const float2*>(bhh + jcol);
    float2 bhz = *reinterpret_cast<const float2*>(bhh + Hh + jcol);
    float2 bhn = *reinterpret_cast<const float2*>(bhh + 2*Hh + jcol);

    float2 hp0 = *reinterpret_cast<const float2*>(hidden + (size_t)gb0*Hh + jcol);
    float2 hp1 = *reinterpret_cast<const float2*>(hidden + (size_t)gb1*Hh + jcol);

    __syncthreads();

    int l8 = lane & 15;
    uint32_t bRow4 = (uint32_t)((lane & 7)*128 + ((lane >> 3) << 4));
    uint32_t aRow  = (uint32_t)((mt*16 + l8)*128 + ((lane >> 4) << 4));

    for (int t = 0; t < Tt; t++){
        // h source: t==0 -> initial buffers (row stride Hh);
        // else -> oh/ol at time t-1 (row stride Tt*Hh)
        const __nv_bfloat16* baseH;
        const __nv_bfloat16* baseL;
        size_t rstride;
        if (t == 0){ baseH = g_hbh; baseL = g_hbl; rstride = Hh; }
        else { baseH = oh + (size_t)(t-1)*Hh; baseL = ol + (size_t)(t-1)*Hh;
               rstride = (size_t)Tt*Hh; }

        if (tid < 64)
            Ms[tid] = dones[(size_t)(b0+tid)*Tt + t] ? 0.f : 1.f;

        // stream h tiles in 4 pipelined groups (2 k-chunks each)
#pragma unroll
        for (int grp = 0; grp < 4; grp++){
#pragma unroll
            for (int i = 0; i < 4; i++){
                int idx = grp*1024 + i*256 + tid;
                int kc = idx >> 9, r = (idx >> 3) & 63, cc = idx & 7;
                uint32_t off = (uint32_t)(kc*8192 + r*128 + cc*16);
                off ^= (off >> 3) & 0x70;
                const void* gh = baseH + (size_t)(b0+r)*rstride + kc*64 + cc*8;
                asm volatile("cp.async.cg.shared.global [%0], [%1], 16;"
                             :: "r"(sb + SW_AH + off), "l"(gh));
                const void* gl = baseL + (size_t)(b0+r)*rstride + kc*64 + cc*8;
                asm volatile("cp.async.cg.shared.global [%0], [%1], 16;"
                             :: "r"(sb + SW_AL + off), "l"(gl));
            }
            asm volatile("cp.async.commit_group;");
        }

        // gi prefetch (latency hides under cp.async wait)
        const float* gp0 = gi + ((size_t)gb0*Tt + t)*H3 + jcol;
        const float* gp1 = gi + ((size_t)gb1*Tt + t)*H3 + jcol;
        float2 gr0 = __ldg(reinterpret_cast<const float2*>(gp0));
        float2 gz0 = __ldg(reinterpret_cast<const float2*>(gp0 + Hh));
        float2 gn0 = __ldg(reinterpret_cast<const float2*>(gp0 + 2*Hh));
        float2 gr1 = __ldg(reinterpret_cast<const float2*>(gp1));
        float2 gz1 = __ldg(reinterpret_cast<const float2*>(gp1 + Hh));
        float2 gn1 = __ldg(reinterpret_cast<const float2*>(gp1 + 2*Hh));

        float acc[3][4];
#pragma unroll
        for (int g=0; g<3; g++)
#pragma unroll
            for (int q=0; q<4; q++) acc[g][q] = 0.f;

        float m0f = 1.f, m1f = 1.f;
        uint32_t am0 = 0xFFFFFFFFu, am1m = 0xFFFFFFFFu;

        // process 2 k-chunks with the given masks
        auto mma2 = [&](int kc0){
#pragma unroll
            for (int kcl = 0; kcl < 2; kcl++){
                int kc = kc0 + kcl;
#pragma unroll
                for (int ksp = 0; ksp < 2; ksp++){
                    uint32_t bh4[3][4], bl4[3][4];
#pragma unroll
                    for (int g = 0; g < 3; g++){
                        uint32_t boff = (uint32_t)((g*2+cb)*8192 + kc*1024 + ksp*64) + bRow4;
                        boff ^= (boff >> 3) & 0x70;
                        asm volatile("ldmatrix.sync.aligned.m8n8.x4.shared.b16 "
                            "{%0,%1,%2,%3}, [%4];"
                            : "=r"(bh4[g][0]),"=r"(bh4[g][1]),
                              "=r"(bh4[g][2]),"=r"(bh4[g][3])
                            : "r"(sb + SW_WH + boff));
                        asm volatile("ldmatrix.sync.aligned.m8n8.x4.shared.b16 "
                            "{%0,%1,%2,%3}, [%4];"
                            : "=r"(bl4[g][0]),"=r"(bl4[g][1]),
                              "=r"(bl4[g][2]),"=r"(bl4[g][3])
                            : "r"(sb + SW_WL + boff));
                    }
#pragma unroll
                    for (int ksi = 0; ksi < 2; ksi++){
                        uint32_t aoff = (uint32_t)(kc*8192 + (ksp*2+ksi)*32) + aRow;
                        aoff ^= (aoff >> 3) & 0x70;
                        uint32_t ah[4], al[4];
                        asm volatile("ldmatrix.sync.aligned.m8n8.x4.shared.b16 "
                            "{%0,%1,%2,%3}, [%4];"
                            : "=r"(ah[0]),"=r"(ah[1]),"=r"(ah[2]),"=r"(ah[3])
                            : "r"(sb + SW_AH + aoff));
                        asm volatile("ldmatrix.sync.aligned.m8n8.x4.shared.b16 "
                            "{%0,%1,%2,%3}, [%4];"
                            : "=r"(al[0]),"=r"(al[1]),"=r"(al[2]),"=r"(al[3])
                            : "r"(sb + SW_AL + aoff));
                        ah[0] &= am0; ah[2] &= am0; ah[1] &= am1m; ah[3] &= am1m;
                        al[0] &= am0; al[2] &= am0; al[1] &= am1m; al[3] &= am1m;
#pragma unroll
                        for (int g = 0; g < 3; g++){
                            uint32_t b0r = bh4[g][ksi*2], b1r = bh4[g][ksi*2+1];
                            uint32_t c0r = bl4[g][ksi*2], c1r = bl4[g][ksi*2+1];
#define MMA1(AV, B0, B1) \
    asm volatile("mma.sync.aligned.m16n8k16.row.col.f32.bf16.bf16.f32 " \
        "{%0,%1,%2,%3}, {%4,%5,%6,%7}, {%8,%9}, {%0,%1,%2,%3};" \
        : "+f"(acc[g][0]), "+f"(acc[g][1]), "+f"(acc[g][2]), "+f"(acc[g][3]) \
        : "r"(AV[0]),"r"(AV[1]),"r"(AV[2]),"r"(AV[3]), "r"(B0),"r"(B1));
                            MMA1(ah, b0r, b1r);
                            MMA1(al, b0r, b1r);
                            MMA1(ah, c0r, c1r);
#undef MMA1
                        }
                    }
                }
            }
        };

        // progressive waits: start mma as soon as each 32KB group lands
        asm volatile("cp.async.wait_group 3;");
        __syncthreads();
        m0f = Ms[mr0]; m1f = Ms[mr1];
        am0  = (m0f != 0.f) ? 0xFFFFFFFFu : 0u;
        am1m = (m1f != 0.f) ? 0xFFFFFFFFu : 0u;
        mma2(0);
        asm volatile("cp.async.wait_group 2;");
        __syncthreads();
        mma2(2);
        asm volatile("cp.async.wait_group 1;");
        __syncthreads();
        mma2(4);
        asm volatile("cp.async.wait_group 0;");
        __syncthreads();
        mma2(6);

        // epilogue (thread-local)
        hp0.x *= m0f; hp0.y *= m0f; hp1.x *= m1f; hp1.y *= m1f;
        float rg0x = sigmoidf_(gr0.x + acc[0][0] + bhr.x);
        float rg0y = sigmoidf_(gr0.y + acc[0][1] + bhr.y);
        float z0x  = sigmoidf_(gz0.x + acc[1][0] + bhz.x);
        float z0y  = sigmoidf_(gz0.y + acc[1][1] + bhz.y);
        float n0x  = tanhf_fast(gn0.x + rg0x*(acc[2][0] + bhn.x));
        float n0y  = tanhf_fast(gn0.y + rg0y*(acc[2][1] + bhn.y));
        hp0.x = (1.f - z0x)*n0x + z0x*hp0.x;
        hp0.y = (1.f - z0y)*n0y + z0y*hp0.y;
        float rg1x = sigmoidf_(gr1.x + acc[0][2] + bhr.x);
        float rg1y = sigmoidf_(gr1.y + acc[0][3] + bhr.y);
        float z1x  = sigmoidf_(gz1.x + acc[1][2] + bhz.x);
        float z1y  = sigmoidf_(gz1.y + acc[1][3] + bhz.y);
        float n1x  = tanhf_fast(gn1.x + rg1x*(acc[2][2] + bhn.x));
        float n1y  = tanhf_fast(gn1.y + rg1y*(acc[2][3] + bhn.y));
        hp1.x = (1.f - z1x)*n1x + z1x*hp1.x;
        hp1.y = (1.f - z1y)*n1y + z1y*hp1.y;

        __nv_bfloat16 hx, hy, lx, ly;
        split_bf(hp0.x, hx, lx); split_bf(hp0.y, hy, ly);
        uint32_t ph0 = pack_bf2(hx, hy), pl0 = pack_bf2(lx, ly);
        split_bf(hp1.x, hx, lx); split_bf(hp1.y, hy, ly);
        uint32_t ph1 = pack_bf2(hx, hy), pl1 = pack_bf2(lx, ly);

        size_t oi0 = (((size_t)gb0*Tt + t)*Hh + jcol) >> 1;
        size_t oi1 = (((size_t)gb1*Tt + t)*Hh + jcol) >> 1;
        reinterpret_cast<uint32_t*>(oh)[oi0] = ph0;
        reinterpret_cast<uint32_t*>(ol)[oi0] = pl0;
        reinterpret_cast<uint32_t*>(oh)[oi1] = ph1;
        reinterpret_cast<uint32_t*>(ol)[oi1] = pl1;
        if (t == Tt-1){
            *reinterpret_cast<float2*>(&hfin[(size_t)gb0*Hh + jcol]) = hp0;
            *reinterpret_cast<float2*>(&hfin[(size_t)gb1*Hh + jcol]) = hp1;
        }

        // per-btile barrier (32 CTAs): release by tid0 after CTA barrier
        __syncthreads();
        if (tid == 0){
            __threadfence();
            unsigned* ctr = &g_bar[bt*Tt + t];
            unsigned a = atomicAdd(ctr, 1u) + 1u;
            if (a < 32u){
                unsigned v;
                do {
                    asm volatile("ld.global.cg.u32 %0, [%1];" : "=r"(v) : "l"(ctr));
                    if (v >= 32u) break;
                    __nanosleep(8);
                } while (true);
            }
            __threadfence();
        }
        __syncthreads();
    }
}

// ---------------- logits: am @ am2_w^T + b, availability mask ---------------
__global__ void __launch_bounds__(256) logits_kernel(
    const float* __restrict__ am, const float* __restrict__ w2,
    const float* __restrict__ b2, const float* __restrict__ avail,
    float* __restrict__ out)
{
    __shared__ float Ws2[Aa*Hh];
    __shared__ float bs[Aa];
    int tid = threadIdx.x;
    for (int idx = tid; idx < Aa*Hh; idx += 256) Ws2[idx] = w2[idx];
    if (tid < Aa) bs[tid] = b2[tid];
    __syncthreads();

    int warp = tid >> 5, lane = tid & 31;
    size_t row = (size_t)blockIdx.x*8 + warp;
    float acc[Aa];
#pragma unroll
    for (int j=0;j<Aa;j++) acc[j] = 0.f;
#pragma unroll 4
    for (int s=0;s<16;s++){
        int k = s*32 + lane;
        float a = am[row*Hh + k];
#pragma unroll
        for (int j=0;j<Aa;j++) acc[j] += a * Ws2[j*Hh + k];
    }
#pragma unroll
    for (int j=0;j<Aa;j++)
#pragma unroll
        for (int o=16;o>0;o>>=1)
            acc[j] += __shfl_xor_sync(0xffffffffu, acc[j], o);
    if (lane == 0){
#pragma unroll
        for (int j=0;j<Aa;j++){
            float av = avail[row*Aa + j];
            out[row*Aa + j] = acc[j] + bs[j] - (1.f - av)*1e10f;
        }
    }
}

// ---------------- host launch ------------------------------------------------
extern "C" void kernel_launch(void* const* d_in, const int* in_sizes, int n_in,
                              void* d_out, int out_size)
{
    const float*    hidden = (const float*)d_in[0];
    const float*    obs    = (const float*)d_in[1];
    const unsigned* dones  = (const unsigned*)d_in[2];
    const float*    avail  = (const float*)d_in[3];
    const float*    in_w   = (const float*)d_in[4];
    const float*    in_b   = (const float*)d_in[5];
    const float*    ln_g   = (const float*)d_in[6];
    const float*    ln_b   = (const float*)d_in[7];
    const float*    wih    = (const float*)d_in[8];
    const float*    whh    = (const float*)d_in[9];
    const float*    bih    = (const float*)d_in[10];
    const float*    bhh    = (const float*)d_in[11];
    const float*    am1_w  = (const float*)d_in[12];
    const float*    am1_b  = (const float*)d_in[13];
    const float*    amln_g = (const float*)d_in[14];
    const float*    amln_b = (const float*)d_in[15];
    const float*    am2_w  = (const float*)d_in[16];
    const float*    am2_b  = (const float*)d_in[17];
    float* out = (float*)d_out;

    void *p_b0, *p_gi, *p_ah, *p_al, *p_wh, *p_wl;
    cudaGetSymbolAddress(&p_b0, g_buf0);
    cudaGetSymbolAddress(&p_gi, g_gi);
    cudaGetSymbolAddress(&p_ah, g_Ah);
    cudaGetSymbolAddress(&p_al, g_Al);
    cudaGetSymbolAddress(&p_wh, g_Wh);
    cudaGetSymbolAddress(&p_wl, g_Wl);
    float* buf0 = (float*)p_b0;
    float* gip  = (float*)p_gi;
    __nv_bfloat16* Ah = (__nv_bfloat16*)p_ah;
    __nv_bfloat16* Al = (__nv_bfloat16*)p_al;
    __nv_bfloat16* Wh = (__nv_bfloat16*)p_wh;
    __nv_bfloat16* Wl = (__nv_bfloat16*)p_wl;

    cudaFuncSetAttribute(gru_scan_mma,
        cudaFuncAttributeMaxDynamicSharedMemorySize, SC_SMEM);
    cudaFuncSetAttribute(gemm_bf16_bias,
        cudaFuncAttributeMaxDynamicSharedMemorySize, GEMM_SMEM3);

    // launch 0: barrier clear + hidden split
    init_misc_kernel<<<128, 256>>>(hidden);
    // launch 1: all weight splits
    conv_w3_kernel<<<(CW_TOT+255)/256, 256>>>(in_w, wih, am1_w);
    // launch 2: obs split
    conv_split_kernel<<<16384, 256>>>(obs, Ah, Al, (size_t)BT*Hh/4);

    dim3 gH(Hh/128, BT/128);       // (4, 1024)
    dim3 gG(H3/128, BT/128);       // (12, 1024)

    // pre-RNN MLP x3 (launch 5 = gemm #2 -> ncu capture)
    gemm_bf16_bias<<<gH, 256, GEMM_SMEM3>>>(Ah, Al, Wh + OFF_INW, Wl + OFF_INW,
                                            in_b, buf0, Hh, Hh);
    ln_relu_conv_kernel<<<BT, 128>>>(buf0, ln_g, ln_b, Ah, Al);
    gemm_bf16_bias<<<gH, 256, GEMM_SMEM3>>>(Ah, Al, Wh + OFF_INW + Hh*Hh,
                                            Wl + OFF_INW + Hh*Hh,
                                            in_b + Hh, buf0, Hh, Hh);
    ln_relu_conv_kernel<<<BT, 128>>>(buf0, ln_g + Hh, ln_b + Hh, Ah, Al);
    gemm_bf16_bias<<<gH, 256, GEMM_SMEM3>>>(Ah, Al, Wh + OFF_INW + 2*Hh*Hh,
                                            Wl + OFF_INW + 2*Hh*Hh,
                                            in_b + 2*Hh, buf0, Hh, Hh);
    ln_relu_conv_kernel<<<BT, 128>>>(buf0, ln_g + 2*Hh, ln_b + 2*Hh, Ah, Al);

    // GRU input projection for all timesteps at once
    gemm_bf16_bias<<<gG, 256, GEMM_SMEM3>>>(Ah, Al, Wh + OFF_WIH, Wl + OFF_WIH,
                                            bih, gip, H3, Hh);

    // sequential GRU scan (persistent; h state lives in Ah/Al = outs)
    gru_scan_mma<<<128, 256, SC_SMEM>>>(gip, whh, bhh, dones, hidden,
                                        Ah, Al, out);

    // actor head: Linear -> LN -> ReLU -> logits
    gemm_bf16_bias<<<gH, 256, GEMM_SMEM3>>>(Ah, Al, Wh + OFF_AM1, Wl + OFF_AM1,
                                            am1_b, buf0, Hh, Hh);
    ln_relu_kernel<<<BT, 128>>>(buf0, amln_g, amln_b);
    logits_kernel<<<BT/8, 256>>>(buf0, am2_w, am2_b, avail, out + (size_t)Bb*Hh);
}

// round 12
// speedup vs baseline: 1.0018x; 1.0018x over previous
#include <cuda_runtime.h>
#include <cuda_bf16.h>
#include <cstdint>
#include <cstddef>

#define Hh 512
#define Aa 16
#define Bb 256
#define Tt 512
#define BT (Bb*Tt)          // 131072 rows
#define H3 1536

// ---------------- device-global scratch (no allocation allowed) -------------
__device__ float g_buf0[(size_t)BT*Hh];             // 256 MB
__device__ float g_gi[(size_t)BT*H3];               // 768 MB
__device__ __nv_bfloat16 g_Ah[(size_t)BT*Hh];       // 128 MB
__device__ __nv_bfloat16 g_Al[(size_t)BT*Hh];       // 128 MB
#define OFF_INW 0
#define OFF_WIH (3*Hh*Hh)
#define OFF_AM1 (3*Hh*Hh + H3*Hh)
#define W_TOTAL (3*Hh*Hh + H3*Hh + Hh*Hh)
__device__ __nv_bfloat16 g_Wh[W_TOTAL];
__device__ __nv_bfloat16 g_Wl[W_TOTAL];
__device__ __nv_bfloat16 g_hbh[Bb*Hh];              // bf16 hi initial hidden
__device__ __nv_bfloat16 g_hbl[Bb*Hh];              // bf16 lo initial hidden
__device__ unsigned g_bar[4*Tt];                    // per-(btile,step) counters

// ---------------- helpers ----------------------------------------------------
__device__ __forceinline__ float sigmoidf_(float x){
    return 1.f / (1.f + __expf(-x));
}
__device__ __forceinline__ float tanhf_fast(float x){
    float e = __expf(2.f*x);
    return 1.f - 2.f/(e + 1.f);
}
__device__ __forceinline__ uint32_t smem_u32(const void* p){
    uint32_t a;
    asm("{ .reg .u64 t; cvta.to.shared.u64 t, %1; cvt.u32.u64 %0, t; }"
        : "=r"(a) : "l"(p));
    return a;
}
__device__ __forceinline__ uint32_t pack_bf2(__nv_bfloat16 a, __nv_bfloat16 b){
    __nv_bfloat162 p = __halves2bfloat162(a, b);
    return *reinterpret_cast<uint32_t*>(&p);
}
__device__ __forceinline__ void split_bf(float x, __nv_bfloat16& h, __nv_bfloat16& l){
    h = __float2bfloat16(x);
    l = __float2bfloat16(x - __bfloat162float(h));
}

// ---------------- init: clear barriers + split hidden -> bf16 hi/lo ---------
__global__ void __launch_bounds__(256) init_misc_kernel(const float* __restrict__ hidden)
{
    int idx = blockIdx.x*256 + threadIdx.x;     // 32768 threads
    if (idx < 4*Tt) g_bar[idx] = 0u;
    float4 v = __ldg(reinterpret_cast<const float4*>(hidden) + idx);
    __nv_bfloat16 h0,h1,h2,h3,l0,l1,l2,l3;
    split_bf(v.x,h0,l0); split_bf(v.y,h1,l1); split_bf(v.z,h2,l2); split_bf(v.w,h3,l3);
    reinterpret_cast<uint2*>(g_hbh)[idx] = make_uint2(pack_bf2(h0,h1), pack_bf2(h2,h3));
    reinterpret_cast<uint2*>(g_hbl)[idx] = make_uint2(pack_bf2(l0,l1), pack_bf2(l2,l3));
}

// ---------------- merged weight split (in_w | wih | am1_w) ------------------
#define CW_N0 (3*Hh*Hh/4)
#define CW_N1 (CW_N0 + H3*Hh/4)
#define CW_TOT (W_TOTAL/4)
__global__ void __launch_bounds__(256) conv_w3_kernel(
    const float* __restrict__ w0, const float* __restrict__ w1,
    const float* __restrict__ w2)
{
    int idx = blockIdx.x*256 + threadIdx.x;
    if (idx >= CW_TOT) return;
    const float* src; int s;
    if (idx < CW_N0){ src = w0; s = idx; }
    else if (idx < CW_N1){ src = w1; s = idx - CW_N0; }
    else { src = w2; s = idx - CW_N1; }
    float4 v = __ldg(reinterpret_cast<const float4*>(src) + s);
    __nv_bfloat16 h0,h1,h2,h3,l0,l1,l2,l3;
    split_bf(v.x,h0,l0); split_bf(v.y,h1,l1); split_bf(v.z,h2,l2); split_bf(v.w,h3,l3);
    reinterpret_cast<uint2*>(g_Wh)[idx] = make_uint2(pack_bf2(h0,h1), pack_bf2(h2,h3));
    reinterpret_cast<uint2*>(g_Wl)[idx] = make_uint2(pack_bf2(l0,l1), pack_bf2(l2,l3));
}

// ---------------- split fp32 -> bf16 hi/lo (obs) ----------------------------
__global__ void __launch_bounds__(256) conv_split_kernel(
    const float* __restrict__ x, __nv_bfloat16* __restrict__ hi,
    __nv_bfloat16* __restrict__ lo, size_t n4)
{
    size_t i = (size_t)blockIdx.x*256 + threadIdx.x;
    size_t stride = (size_t)gridDim.x*256;
    for (; i < n4; i += stride){
        float4 v = __ldg(reinterpret_cast<const float4*>(x) + i);
        __nv_bfloat16 h0,h1,h2,h3,l0,l1,l2,l3;
        split_bf(v.x,h0,l0); split_bf(v.y,h1,l1); split_bf(v.z,h2,l2); split_bf(v.w,h3,l3);
        reinterpret_cast<uint2*>(hi)[i] = make_uint2(pack_bf2(h0,h1), pack_bf2(h2,h3));
        reinterpret_cast<uint2*>(lo)[i] = make_uint2(pack_bf2(l0,l1), pack_bf2(l2,l3));
    }
}

// ---------------- bf16 tensor-core GEMM: C = A @ B^T + bias -----------------
#define STG_B 65536
#define GEMM_SMEM3 (3*STG_B + 512)

__global__ void __launch_bounds__(256) gemm_bf16_bias(
    const __nv_bfloat16* __restrict__ Ah, const __nv_bfloat16* __restrict__ Al,
    const __nv_bfloat16* __restrict__ Bh, const __nv_bfloat16* __restrict__ Bl,
    const float* __restrict__ bias, float* __restrict__ C, int N, int K)
{
    extern __shared__ char gsm[];
    uint32_t sb = smem_u32(gsm);
    float* biasS = reinterpret_cast<float*>(gsm + 3*STG_B);

    int tid = threadIdx.x;
    int lane = tid & 31, wid = tid >> 5;
    int wm = wid & 1, wn = wid >> 1;
    int n0 = blockIdx.x * 128, m0 = blockIdx.y * 128;

    if (tid < 128) biasS[tid] = bias[n0 + tid];

    float acc[4][4][4];
#pragma unroll
    for (int mt=0; mt<4; mt++)
#pragma unroll
        for (int nt=0; nt<4; nt++)
#pragma unroll
            for (int q=0; q<4; q++) acc[mt][nt][q] = 0.f;

    const int tot = K >> 6;
    const __nv_bfloat16* srcs[4] = {Ah, Al, Bh, Bl};

    auto issue = [&](int c){
        uint32_t base = sb + (uint32_t)(c % 3)*STG_B;
        int kk = c << 6;
#pragma unroll
        for (int tI = 0; tI < 4; tI++){
            const __nv_bfloat16* sp = srcs[tI];
            int rb = (tI < 2) ? m0 : n0;
            uint32_t tBase = base + tI*16384;
#pragma unroll
            for (int i = 0; i < 4; i++){
                int idx = i*256 + tid;
                int r = idx >> 3, cc = idx & 7;
                uint32_t so = (uint32_t)(r*128 + cc*16);
                so ^= (so >> 3) & 0x70;
                const void* g = sp + (size_t)(rb + r)*K + kk + cc*8;
                asm volatile("cp.async.cg.shared.global [%0], [%1], 16;"
                             :: "r"(tBase + so), "l"(g));
            }
        }
        asm volatile("cp.async.commit_group;");
    };

    issue(0);
    if (tot > 1) issue(1);

    for (int c = 0; c < tot; c++){
        if (c + 2 < tot){
            issue(c + 2);
            asm volatile("cp.async.wait_group 2;");
        } else if (c + 1 < tot){
            asm volatile("cp.async.wait_group 1;");
        } else {
            asm volatile("cp.async.wait_group 0;");
        }
        __syncthreads();
        uint32_t base  = sb + (uint32_t)(c % 3)*STG_B;
        uint32_t aHB = base, aLB = base + 16384;
        uint32_t bHB = base + 32768, bLB = base + 49152;

        int mat = lane >> 3;
        int rowp = ((mat & 2) << 2) + (lane & 7);
        int khalf = (mat & 1) << 4;

#pragma unroll
        for (int ks = 0; ks < 4; ks++){
            uint32_t ah[4][4], al[4][4], bh[4][2], bl[4][2];
#pragma unroll
            for (int mt = 0; mt < 4; mt++){
                uint32_t off = (uint32_t)((wm*64 + mt*16 + (lane & 15))*128
                              + ks*32 + ((lane >> 4) << 4));
                off ^= (off >> 3) & 0x70;
                asm volatile("ldmatrix.sync.aligned.m8n8.x4.shared.b16 "
                    "{%0,%1,%2,%3}, [%4];"
                    : "=r"(ah[mt][0]),"=r"(ah[mt][1]),"=r"(ah[mt][2]),"=r"(ah[mt][3])
                    : "r"(aHB + off));
                asm volatile("ldmatrix.sync.aligned.m8n8.x4.shared.b16 "
                    "{%0,%1,%2,%3}, [%4];"
                    : "=r"(al[mt][0]),"=r"(al[mt][1]),"=r"(al[mt][2]),"=r"(al[mt][3])
                    : "r"(aLB + off));
            }
#pragma unroll
            for (int ntp = 0; ntp < 2; ntp++){
                uint32_t off = (uint32_t)((wn*32 + ntp*16 + rowp)*128
                              + ks*32 + khalf);
                off ^= (off >> 3) & 0x70;
                asm volatile("ldmatrix.sync.aligned.m8n8.x4.shared.b16 "
                    "{%0,%1,%2,%3}, [%4];"
                    : "=r"(bh[ntp*2][0]),"=r"(bh[ntp*2][1]),
                      "=r"(bh[ntp*2+1][0]),"=r"(bh[ntp*2+1][1])
                    : "r"(bHB + off));
                asm volatile("ldmatrix.sync.aligned.m8n8.x4.shared.b16 "
                    "{%0,%1,%2,%3}, [%4];"
                    : "=r"(bl[ntp*2][0]),"=r"(bl[ntp*2][1]),
                      "=r"(bl[ntp*2+1][0]),"=r"(bl[ntp*2+1][1])
                    : "r"(bLB + off));
            }
#define MMA16(AV, BV, mt, nt) \
    asm volatile("mma.sync.aligned.m16n8k16.row.col.f32.bf16.bf16.f32 " \
        "{%0,%1,%2,%3}, {%4,%5,%6,%7}, {%8,%9}, {%0,%1,%2,%3};" \
        : "+f"(acc[mt][nt][0]), "+f"(acc[mt][nt][1]), \
          "+f"(acc[mt][nt][2]), "+f"(acc[mt][nt][3]) \
        : "r"(AV[mt][0]),"r"(AV[mt][1]),"r"(AV[mt][2]),"r"(AV[mt][3]), \
          "r"(BV[nt][0]),"r"(BV[nt][1]));
#pragma unroll
            for (int mt = 0; mt < 4; mt++)
#pragma unroll
                for (int nt = 0; nt < 4; nt++){
                    MMA16(ah, bh, mt, nt);
                    MMA16(al, bh, mt, nt);
                    MMA16(ah, bl, mt, nt);
                }
#undef MMA16
        }
        __syncthreads();
    }

#pragma unroll
    for (int mt = 0; mt < 4; mt++){
        int r0 = m0 + wm*64 + mt*16 + (lane >> 2);
#pragma unroll
        for (int nt = 0; nt < 4; nt++){
            int nl = wn*32 + nt*8 + (lane & 3)*2;
            float bx = biasS[nl], by = biasS[nl+1];
            float2 v0 = make_float2(acc[mt][nt][0] + bx, acc[mt][nt][1] + by);
            float2 v1 = make_float2(acc[mt][nt][2] + bx, acc[mt][nt][3] + by);
            *reinterpret_cast<float2*>(&C[(size_t)r0*N + n0 + nl]) = v0;
            *reinterpret_cast<float2*>(&C[(size_t)(r0+8)*N + n0 + nl]) = v1;
        }
    }
}

// ---------------- LayerNorm + ReLU in place (fp32) --------------------------
__global__ void __launch_bounds__(128) ln_relu_kernel(
    float* __restrict__ X, const float* __restrict__ gamma,
    const float* __restrict__ beta)
{
    size_t row = blockIdx.x;
    float* x = X + row*Hh;
    int tid = threadIdx.x;
    float4 v = *reinterpret_cast<float4*>(&x[tid*4]);
    float s = v.x+v.y+v.z+v.w;
    float q = v.x*v.x + v.y*v.y + v.z*v.z + v.w*v.w;
#pragma unroll
    for (int o=16;o>0;o>>=1){
        s += __shfl_xor_sync(0xffffffffu, s, o);
        q += __shfl_xor_sync(0xffffffffu, q, o);
    }
    __shared__ float ss[4], qq[4];
    if ((tid & 31) == 0){ ss[tid>>5] = s; qq[tid>>5] = q; }
    __syncthreads();
    s = ss[0]+ss[1]+ss[2]+ss[3];
    q = qq[0]+qq[1]+qq[2]+qq[3];
    float mu  = s * (1.f/Hh);
    float var = q * (1.f/Hh) - mu*mu;
    float inv = rsqrtf(var + 1e-5f);
    float4 g4 = *reinterpret_cast<const float4*>(&gamma[tid*4]);
    float4 b4 = *reinterpret_cast<const float4*>(&beta[tid*4]);
    v.x = fmaxf((v.x-mu)*inv*g4.x + b4.x, 0.f);
    v.y = fmaxf((v.y-mu)*inv*g4.y + b4.y, 0.f);
    v.z = fmaxf((v.z-mu)*inv*g4.z + b4.z, 0.f);
    v.w = fmaxf((v.w-mu)*inv*g4.w + b4.w, 0.f);
    *reinterpret_cast<float4*>(&x[tid*4]) = v;
}

// ---------------- LayerNorm + ReLU -> bf16 hi/lo split ----------------------
__global__ void __launch_bounds__(128) ln_relu_conv_kernel(
    const float* __restrict__ X, const float* __restrict__ gamma,
    const float* __restrict__ beta,
    __nv_bfloat16* __restrict__ oh, __nv_bfloat16* __restrict__ ol)
{
    size_t row = blockIdx.x;
    const float* x = X + row*Hh;
    int tid = threadIdx.x;
    float4 v = *reinterpret_cast<const float4*>(&x[tid*4]);
    float s = v.x+v.y+v.z+v.w;
    float q = v.x*v.x + v.y*v.y + v.z*v.z + v.w*v.w;
#pragma unroll
    for (int o=16;o>0;o>>=1){
        s += __shfl_xor_sync(0xffffffffu, s, o);
        q += __shfl_xor_sync(0xffffffffu, q, o);
    }
    __shared__ float ss[4], qq[4];
    if ((tid & 31) == 0){ ss[tid>>5] = s; qq[tid>>5] = q; }
    __syncthreads();
    s = ss[0]+ss[1]+ss[2]+ss[3];
    q = qq[0]+qq[1]+qq[2]+qq[3];
    float mu  = s * (1.f/Hh);
    float var = q * (1.f/Hh) - mu*mu;
    float inv = rsqrtf(var + 1e-5f);
    float4 g4 = *reinterpret_cast<const float4*>(&gamma[tid*4]);
    float4 b4 = *reinterpret_cast<const float4*>(&beta[tid*4]);
    v.x = fmaxf((v.x-mu)*inv*g4.x + b4.x, 0.f);
    v.y = fmaxf((v.y-mu)*inv*g4.y + b4.y, 0.f);
    v.z = fmaxf((v.z-mu)*inv*g4.z + b4.z, 0.f);
    v.w = fmaxf((v.w-mu)*inv*g4.w + b4.w, 0.f);
    __nv_bfloat16 h0,h1,h2,h3,l0,l1,l2,l3;
    split_bf(v.x,h0,l0); split_bf(v.y,h1,l1); split_bf(v.z,h2,l2); split_bf(v.w,h3,l3);
    size_t i = row*128 + tid;
    reinterpret_cast<uint2*>(oh)[i] = make_uint2(pack_bf2(h0,h1), pack_bf2(h2,h3));
    reinterpret_cast<uint2*>(ol)[i] = make_uint2(pack_bf2(l0,l1), pack_bf2(l2,l3));
}

// ---------------- persistent GRU scan: split-bf16 mma ------------------------
// h state lives directly in the outs arrays (oh/ol): step t reads row
// b*Tt+(t-1) (or the initial-hidden buffer at t=0) and writes row b*Tt+t.
#define SW_WH 0
#define SW_WL 49152
#define SW_AH 98304
#define SW_AL 163840
#define SW_MS 229376
#define SC_SMEM (229376 + 256)

__global__ void __launch_bounds__(256) gru_scan_mma(
    const float* __restrict__ gi,        // [B*T][3H] (includes bih)
    const float* __restrict__ whh,       // [3H][H]
    const float* __restrict__ bhh,       // [3H]
    const unsigned* __restrict__ dones,  // [B][T] 4-byte words
    const float* __restrict__ hidden,    // [B][H] fp32 h_0
    __nv_bfloat16* __restrict__ oh,      // [B][T][H] bf16 hi (state + outs)
    __nv_bfloat16* __restrict__ ol,
    float* __restrict__ hfin)            // [B][H] fp32 -> d_out head
{
    extern __shared__ char ssm[];
    uint32_t sb = smem_u32(ssm);
    float* Ms = reinterpret_cast<float*>(ssm + SW_MS);

    int tid = threadIdx.x;
    int lane = tid & 31, wid = tid >> 5;
    int mt = wid & 3, cb = wid >> 2;
    int bt = blockIdx.x >> 5, jt = blockIdx.x & 31;
    int b0 = bt*64, j0 = jt*16;

    // load Whh slice (48 rows x 512 k) into smem as bf16 hi/lo, swizzled
    for (int idx = tid; idx < 48*512; idx += 256){
        int rr = idx >> 9;          // 0..47 = g*16 + jc
        int k  = idx & 511;
        int g = rr >> 4, jc = rr & 15;
        int cbw = jc >> 3, rw = jc & 7;
        float w = whh[(size_t)(g*Hh + j0 + jc)*Hh + k];
        __nv_bfloat16 h, l; split_bf(w, h, l);
        int kc = k >> 6, kk = k & 63;
        uint32_t off = (uint32_t)((g*2+cbw)*8192 + kc*1024 + rw*128 + kk*2);
        uint32_t sw = off ^ ((off >> 3) & 0x70);
        *reinterpret_cast<__nv_bfloat16*>(ssm + SW_WH + sw) = h;
        *reinterpret_cast<__nv_bfloat16*>(ssm + SW_WL + sw) = l;
    }

    int r0l = lane >> 2;                 // 0..7
    int mr0 = mt*16 + r0l, mr1 = mr0 + 8;
    int gb0 = b0 + mr0,   gb1 = b0 + mr1;
    int jcol = j0 + cb*8 + (lane & 3)*2;

    float2 bhr = *reinterpret_cast<const float2*>(bhh + jcol);
    float2 bhz = *reinterpret_cast<const float2*>(bhh + Hh + jcol);
    float2 bhn = *reinterpret_cast<const float2*>(bhh + 2*Hh + jcol);

    float2 hp0 = *reinterpret_cast<const float2*>(hidden + (size_t)gb0*Hh + jcol);
    float2 hp1 = *reinterpret_cast<const float2*>(hidden + (size_t)gb1*Hh + jcol);

    __syncthreads();

    int l8 = lane & 15;
    uint32_t bRow4 = (uint32_t)((lane & 7)*128 + ((lane >> 3) << 4));
    uint32_t aRow  = (uint32_t)((mt*16 + l8)*128 + ((lane >> 4) << 4));

    for (int t = 0; t < Tt; t++){
        // h source: t==0 -> initial buffers (row stride Hh);
        // else -> oh/ol at time t-1 (row stride Tt*Hh)
        const __nv_bfloat16* baseH;
        const __nv_bfloat16* baseL;
        size_t rstride;
        if (t == 0){ baseH = g_hbh; baseL = g_hbl; rstride = Hh; }
        else { baseH = oh + (size_t)(t-1)*Hh; baseL = ol + (size_t)(t-1)*Hh;
               rstride = (size_t)Tt*Hh; }

        if (tid < 64)
            Ms[tid] = dones[(size_t)(b0+tid)*Tt + t] ? 0.f : 1.f;

        // stream h tiles in 4 pipelined groups (2 k-chunks each)
#pragma unroll
        for (int grp = 0; grp < 4; grp++){
#pragma unroll
            for (int i = 0; i < 4; i++){
                int idx = grp*1024 + i*256 + tid;
                int kc = idx >> 9, r = (idx >> 3) & 63, cc = idx & 7;
                uint32_t off = (uint32_t)(kc*8192 + r*128 + cc*16);
                off ^= (off >> 3) & 0x70;
                const void* gh = baseH + (size_t)(b0+r)*rstride + kc*64 + cc*8;
                asm volatile("cp.async.cg.shared.global [%0], [%1], 16;"
                             :: "r"(sb + SW_AH + off), "l"(gh));
                const void* gl = baseL + (size_t)(b0+r)*rstride + kc*64 + cc*8;
                asm volatile("cp.async.cg.shared.global [%0], [%1], 16;"
                             :: "r"(sb + SW_AL + off), "l"(gl));
            }
            asm volatile("cp.async.commit_group;");
        }

        // gi prefetch (latency hides under cp.async wait)
        const float* gp0 = gi + ((size_t)gb0*Tt + t)*H3 + jcol;
        const float* gp1 = gi + ((size_t)gb1*Tt + t)*H3 + jcol;
        float2 gr0 = __ldg(reinterpret_cast<const float2*>(gp0));
        float2 gz0 = __ldg(reinterpret_cast<const float2*>(gp0 + Hh));
        float2 gn0 = __ldg(reinterpret_cast<const float2*>(gp0 + 2*Hh));
        float2 gr1 = __ldg(reinterpret_cast<const float2*>(gp1));
        float2 gz1 = __ldg(reinterpret_cast<const float2*>(gp1 + Hh));
        float2 gn1 = __ldg(reinterpret_cast<const float2*>(gp1 + 2*Hh));

        float acc[3][4];
#pragma unroll
        for (int g=0; g<3; g++)
#pragma unroll
            for (int q=0; q<4; q++) acc[g][q] = 0.f;

        float m0f = 1.f, m1f = 1.f;
        uint32_t am0 = 0xFFFFFFFFu, am1m = 0xFFFFFFFFu;

        // process 2 k-chunks; mma issue order rotates accumulators
        // (acc[0]->acc[1]->acc[2]) so consecutive mma never share an
        // accumulator (RAW distance 3 covers HMMA latency at rt 8).
        auto mma2 = [&](int kc0){
#pragma unroll
            for (int kcl = 0; kcl < 2; kcl++){
                int kc = kc0 + kcl;
#pragma unroll
                for (int ksp = 0; ksp < 2; ksp++){
                    uint32_t bh4[3][4], bl4[3][4];
#pragma unroll
                    for (int g = 0; g < 3; g++){
                        uint32_t boff = (uint32_t)((g*2+cb)*8192 + kc*1024 + ksp*64) + bRow4;
                        boff ^= (boff >> 3) & 0x70;
                        asm volatile("ldmatrix.sync.aligned.m8n8.x4.shared.b16 "
                            "{%0,%1,%2,%3}, [%4];"
                            : "=r"(bh4[g][0]),"=r"(bh4[g][1]),
                              "=r"(bh4[g][2]),"=r"(bh4[g][3])
                            : "r"(sb + SW_WH + boff));
                        asm volatile("ldmatrix.sync.aligned.m8n8.x4.shared.b16 "
                            "{%0,%1,%2,%3}, [%4];"
                            : "=r"(bl4[g][0]),"=r"(bl4[g][1]),
                              "=r"(bl4[g][2]),"=r"(bl4[g][3])
                            : "r"(sb + SW_WL + boff));
                    }
#pragma unroll
                    for (int ksi = 0; ksi < 2; ksi++){
                        uint32_t aoff = (uint32_t)(kc*8192 + (ksp*2+ksi)*32) + aRow;
                        aoff ^= (aoff >> 3) & 0x70;
                        uint32_t ah[4], al[4];
                        asm volatile("ldmatrix.sync.aligned.m8n8.x4.shared.b16 "
                            "{%0,%1,%2,%3}, [%4];"
                            : "=r"(ah[0]),"=r"(ah[1]),"=r"(ah[2]),"=r"(ah[3])
                            : "r"(sb + SW_AH + aoff));
                        asm volatile("ldmatrix.sync.aligned.m8n8.x4.shared.b16 "
                            "{%0,%1,%2,%3}, [%4];"
                            : "=r"(al[0]),"=r"(al[1]),"=r"(al[2]),"=r"(al[3])
                            : "r"(sb + SW_AL + aoff));
                        ah[0] &= am0; ah[2] &= am0; ah[1] &= am1m; ah[3] &= am1m;
                        al[0] &= am0; al[2] &= am0; al[1] &= am1m; al[3] &= am1m;
#define MMA1(AV, B0, B1, g) \
    asm volatile("mma.sync.aligned.m16n8k16.row.col.f32.bf16.bf16.f32 " \
        "{%0,%1,%2,%3}, {%4,%5,%6,%7}, {%8,%9}, {%0,%1,%2,%3};" \
        : "+f"(acc[g][0]), "+f"(acc[g][1]), "+f"(acc[g][2]), "+f"(acc[g][3]) \
        : "r"(AV[0]),"r"(AV[1]),"r"(AV[2]),"r"(AV[3]), "r"(B0),"r"(B1));
                        // combo-outer / gate-inner: accumulator rotation
#pragma unroll
                        for (int g = 0; g < 3; g++)
                            MMA1(ah, bh4[g][ksi*2], bh4[g][ksi*2+1], g);
#pragma unroll
                        for (int g = 0; g < 3; g++)
                            MMA1(al, bh4[g][ksi*2], bh4[g][ksi*2+1], g);
#pragma unroll
                        for (int g = 0; g < 3; g++)
                            MMA1(ah, bl4[g][ksi*2], bl4[g][ksi*2+1], g);
#undef MMA1
                    }
                }
            }
        };

        // progressive waits: start mma as soon as each 32KB group lands
        asm volatile("cp.async.wait_group 3;");
        __syncthreads();
        m0f = Ms[mr0]; m1f = Ms[mr1];
        am0  = (m0f != 0.f) ? 0xFFFFFFFFu : 0u;
        am1m = (m1f != 0.f) ? 0xFFFFFFFFu : 0u;
        mma2(0);
        asm volatile("cp.async.wait_group 2;");
        __syncthreads();
        mma2(2);
        asm volatile("cp.async.wait_group 1;");
        __syncthreads();
        mma2(4);
        asm volatile("cp.async.wait_group 0;");
        __syncthreads();
        mma2(6);

        // epilogue (thread-local)
        hp0.x *= m0f; hp0.y *= m0f; hp1.x *= m1f; hp1.y *= m1f;
        float rg0x = sigmoidf_(gr0.x + acc[0][0] + bhr.x);
        float rg0y = sigmoidf_(gr0.y + acc[0][1] + bhr.y);
        float z0x  = sigmoidf_(gz0.x + acc[1][0] + bhz.x);
        float z0y  = sigmoidf_(gz0.y + acc[1][1] + bhz.y);
        float n0x  = tanhf_fast(gn0.x + rg0x*(acc[2][0] + bhn.x));
        float n0y  = tanhf_fast(gn0.y + rg0y*(acc[2][1] + bhn.y));
        hp0.x = (1.f - z0x)*n0x + z0x*hp0.x;
        hp0.y = (1.f - z0y)*n0y + z0y*hp0.y;
        float rg1x = sigmoidf_(gr1.x + acc[0][2] + bhr.x);
        float rg1y = sigmoidf_(gr1.y + acc[0][3] + bhr.y);
        float z1x  = sigmoidf_(gz1.x + acc[1][2] + bhz.x);
        float z1y  = sigmoidf_(gz1.y + acc[1][3] + bhz.y);
        float n1x  = tanhf_fast(gn1.x + rg1x*(acc[2][2] + bhn.x));
        float n1y  = tanhf_fast(gn1.y + rg1y*(acc[2][3] + bhn.y));
        hp1.x = (1.f - z1x)*n1x + z1x*hp1.x;
        hp1.y = (1.f - z1y)*n1y + z1y*hp1.y;

        __nv_bfloat16 hx, hy, lx, ly;
        split_bf(hp0.x, hx, lx); split_bf(hp0.y, hy, ly);
        uint32_t ph0 = pack_bf2(hx, hy), pl0 = pack_bf2(lx, ly);
        split_bf(hp1.x, hx, lx); split_bf(hp1.y, hy, ly);
        uint32_t ph1 = pack_bf2(hx, hy), pl1 = pack_bf2(lx, ly);

        size_t oi0 = (((size_t)gb0*Tt + t)*Hh + jcol) >> 1;
        size_t oi1 = (((size_t)gb1*Tt + t)*Hh + jcol) >> 1;
        reinterpret_cast<uint32_t*>(oh)[oi0] = ph0;
        reinterpret_cast<uint32_t*>(ol)[oi0] = pl0;
        reinterpret_cast<uint32_t*>(oh)[oi1] = ph1;
        reinterpret_cast<uint32_t*>(ol)[oi1] = pl1;
        if (t == Tt-1){
            *reinterpret_cast<float2*>(&hfin[(size_t)gb0*Hh + jcol]) = hp0;
            *reinterpret_cast<float2*>(&hfin[(size_t)gb1*Hh + jcol]) = hp1;
        }

        // per-btile barrier (32 CTAs): release by tid0 after CTA barrier
        __syncthreads();
        if (tid == 0){
            __threadfence();
            unsigned* ctr = &g_bar[bt*Tt + t];
            unsigned a = atomicAdd(ctr, 1u) + 1u;
            if (a < 32u){
                unsigned v;
                do {
                    asm volatile("ld.global.cg.u32 %0, [%1];" : "=r"(v) : "l"(ctr));
                    if (v >= 32u) break;
                    __nanosleep(8);
                } while (true);
            }
            __threadfence();
        }
        __syncthreads();
    }
}

// ---------------- logits: am @ am2_w^T + b, availability mask ---------------
__global__ void __launch_bounds__(256) logits_kernel(
    const float* __restrict__ am, const float* __restrict__ w2,
    const float* __restrict__ b2, const float* __restrict__ avail,
    float* __restrict__ out)
{
    __shared__ float Ws2[Aa*Hh];
    __shared__ float bs[Aa];
    int tid = threadIdx.x;
    for (int idx = tid; idx < Aa*Hh; idx += 256) Ws2[idx] = w2[idx];
    if (tid < Aa) bs[tid] = b2[tid];
    __syncthreads();

    int warp = tid >> 5, lane = tid & 31;
    size_t row = (size_t)blockIdx.x*8 + warp;
    float acc[Aa];
#pragma unroll
    for (int j=0;j<Aa;j++) acc[j] = 0.f;
#pragma unroll 4
    for (int s=0;s<16;s++){
        int k = s*32 + lane;
        float a = am[row*Hh + k];
#pragma unroll
        for (int j=0;j<Aa;j++) acc[j] += a * Ws2[j*Hh + k];
    }
#pragma unroll
    for (int j=0;j<Aa;j++)
#pragma unroll
        for (int o=16;o>0;o>>=1)
            acc[j] += __shfl_xor_sync(0xffffffffu, acc[j], o);
    if (lane == 0){
#pragma unroll
        for (int j=0;j<Aa;j++){
            float av = avail[row*Aa + j];
            out[row*Aa + j] = acc[j] + bs[j] - (1.f - av)*1e10f;
        }
    }
}

// ---------------- host launch ------------------------------------------------
extern "C" void kernel_launch(void* const* d_in, const int* in_sizes, int n_in,
                              void* d_out, int out_size)
{
    const float*    hidden = (const float*)d_in[0];
    const float*    obs    = (const float*)d_in[1];
    const unsigned* dones  = (const unsigned*)d_in[2];
    const float*    avail  = (const float*)d_in[3];
    const float*    in_w   = (const float*)d_in[4];
    const float*    in_b   = (const float*)d_in[5];
    const float*    ln_g   = (const float*)d_in[6];
    const float*    ln_b   = (const float*)d_in[7];
    const float*    wih    = (const float*)d_in[8];
    const float*    whh    = (const float*)d_in[9];
    const float*    bih    = (const float*)d_in[10];
    const float*    bhh    = (const float*)d_in[11];
    const float*    am1_w  = (const float*)d_in[12];
    const float*    am1_b  = (const float*)d_in[13];
    const float*    amln_g = (const float*)d_in[14];
    const float*    amln_b = (const float*)d_in[15];
    const float*    am2_w  = (const float*)d_in[16];
    const float*    am2_b  = (const float*)d_in[17];
    float* out = (float*)d_out;

    void *p_b0, *p_gi, *p_ah, *p_al, *p_wh, *p_wl;
    cudaGetSymbolAddress(&p_b0, g_buf0);
    cudaGetSymbolAddress(&p_gi, g_gi);
    cudaGetSymbolAddress(&p_ah, g_Ah);
    cudaGetSymbolAddress(&p_al, g_Al);
    cudaGetSymbolAddress(&p_wh, g_Wh);
    cudaGetSymbolAddress(&p_wl, g_Wl);
    float* buf0 = (float*)p_b0;
    float* gip  = (float*)p_gi;
    __nv_bfloat16* Ah = (__nv_bfloat16*)p_ah;
    __nv_bfloat16* Al = (__nv_bfloat16*)p_al;
    __nv_bfloat16* Wh = (__nv_bfloat16*)p_wh;
    __nv_bfloat16* Wl = (__nv_bfloat16*)p_wl;

    cudaFuncSetAttribute(gru_scan_mma,
        cudaFuncAttributeMaxDynamicSharedMemorySize, SC_SMEM);
    cudaFuncSetAttribute(gemm_bf16_bias,
        cudaFuncAttributeMaxDynamicSharedMemorySize, GEMM_SMEM3);

    // launch 0: barrier clear + hidden split
    init_misc_kernel<<<128, 256>>>(hidden);
    // launch 1: all weight splits
    conv_w3_kernel<<<(CW_TOT+255)/256, 256>>>(in_w, wih, am1_w);
    // launch 2: obs split
    conv_split_kernel<<<16384, 256>>>(obs, Ah, Al, (size_t)BT*Hh/4);

    dim3 gH(Hh/128, BT/128);       // (4, 1024)
    dim3 gG(H3/128, BT/128);       // (12, 1024)

    // pre-RNN MLP x3 (launch 5 = gemm #2 -> ncu capture)
    gemm_bf16_bias<<<gH, 256, GEMM_SMEM3>>>(Ah, Al, Wh + OFF_INW, Wl + OFF_INW,
                                            in_b, buf0, Hh, Hh);
    ln_relu_conv_kernel<<<BT, 128>>>(buf0, ln_g, ln_b, Ah, Al);
    gemm_bf16_bias<<<gH, 256, GEMM_SMEM3>>>(Ah, Al, Wh + OFF_INW + Hh*Hh,
                                            Wl + OFF_INW + Hh*Hh,
                                            in_b + Hh, buf0, Hh, Hh);
    ln_relu_conv_kernel<<<BT, 128>>>(buf0, ln_g + Hh, ln_b + Hh, Ah, Al);
    gemm_bf16_bias<<<gH, 256, GEMM_SMEM3>>>(Ah, Al, Wh + OFF_INW + 2*Hh*Hh,
                                            Wl + OFF_INW + 2*Hh*Hh,
                                            in_b + 2*Hh, buf0, Hh, Hh);
    ln_relu_conv_kernel<<<BT, 128>>>(buf0, ln_g + 2*Hh, ln_b + 2*Hh, Ah, Al);

    // GRU input projection for all timesteps at once
    gemm_bf16_bias<<<gG, 256, GEMM_SMEM3>>>(Ah, Al, Wh + OFF_WIH, Wl + OFF_WIH,
                                            bih, gip, H3, Hh);

    // sequential GRU scan (persistent; h state lives in Ah/Al = outs)
    gru_scan_mma<<<128, 256, SC_SMEM>>>(gip, whh, bhh, dones, hidden,
                                        Ah, Al, out);

    // actor head: Linear -> LN -> ReLU -> logits
    gemm_bf16_bias<<<gH, 256, GEMM_SMEM3>>>(Ah, Al, Wh + OFF_AM1, Wl + OFF_AM1,
                                            am1_b, buf0, Hh, Hh);
    ln_relu_kernel<<<BT, 128>>>(buf0, amln_g, amln_b);
    logits_kernel<<<BT/8, 256>>>(buf0, am2_w, am2_b, avail, out + (size_t)Bb*Hh);
}

// round 13
// speedup vs baseline: 1.0342x; 1.0323x over previous
#include <cuda_runtime.h>
#include <cuda_bf16.h>
#include <cstdint>
#include <cstddef>

#define Hh 512
#define Aa 16
#define Bb 256
#define Tt 512
#define BT (Bb*Tt)          // 131072 rows
#define H3 1536

// ---------------- device-global scratch (no allocation allowed) -------------
__device__ float g_buf0[(size_t)BT*Hh];             // 256 MB
__device__ float g_gi[(size_t)BT*H3];               // 768 MB
__device__ __nv_bfloat16 g_Ah[(size_t)BT*Hh];       // 128 MB
__device__ __nv_bfloat16 g_Al[(size_t)BT*Hh];       // 128 MB
#define OFF_INW 0
#define OFF_WIH (3*Hh*Hh)
#define OFF_AM1 (3*Hh*Hh + H3*Hh)
#define W_TOTAL (3*Hh*Hh + H3*Hh + Hh*Hh)
__device__ __nv_bfloat16 g_Wh[W_TOTAL];
__device__ __nv_bfloat16 g_Wl[W_TOTAL];
__device__ __nv_bfloat16 g_hbh[Bb*Hh];              // bf16 hi initial hidden
__device__ __nv_bfloat16 g_hbl[Bb*Hh];              // bf16 lo initial hidden
__device__ unsigned g_bar[4*Tt];                    // per-(btile,step) counters

// ---------------- helpers ----------------------------------------------------
__device__ __forceinline__ float sigmoidf_(float x){
    return 1.f / (1.f + __expf(-x));
}
__device__ __forceinline__ float tanhf_fast(float x){
    float e = __expf(2.f*x);
    return 1.f - 2.f/(e + 1.f);
}
__device__ __forceinline__ uint32_t smem_u32(const void* p){
    uint32_t a;
    asm("{ .reg .u64 t; cvta.to.shared.u64 t, %1; cvt.u32.u64 %0, t; }"
        : "=r"(a) : "l"(p));
    return a;
}
__device__ __forceinline__ uint32_t pack_bf2(__nv_bfloat16 a, __nv_bfloat16 b){
    __nv_bfloat162 p = __halves2bfloat162(a, b);
    return *reinterpret_cast<uint32_t*>(&p);
}
__device__ __forceinline__ void split_bf(float x, __nv_bfloat16& h, __nv_bfloat16& l){
    h = __float2bfloat16(x);
    l = __float2bfloat16(x - __bfloat162float(h));
}

// ---------------- init: clear barriers + split hidden -> bf16 hi/lo ---------
__global__ void __launch_bounds__(256) init_misc_kernel(const float* __restrict__ hidden)
{
    int idx = blockIdx.x*256 + threadIdx.x;     // 32768 threads
    if (idx < 4*Tt) g_bar[idx] = 0u;
    float4 v = __ldg(reinterpret_cast<const float4*>(hidden) + idx);
    __nv_bfloat16 h0,h1,h2,h3,l0,l1,l2,l3;
    split_bf(v.x,h0,l0); split_bf(v.y,h1,l1); split_bf(v.z,h2,l2); split_bf(v.w,h3,l3);
    reinterpret_cast<uint2*>(g_hbh)[idx] = make_uint2(pack_bf2(h0,h1), pack_bf2(h2,h3));
    reinterpret_cast<uint2*>(g_hbl)[idx] = make_uint2(pack_bf2(l0,l1), pack_bf2(l2,l3));
}

// ---------------- merged weight split (in_w | wih | am1_w) ------------------
#define CW_N0 (3*Hh*Hh/4)
#define CW_N1 (CW_N0 + H3*Hh/4)
#define CW_TOT (W_TOTAL/4)
__global__ void __launch_bounds__(256) conv_w3_kernel(
    const float* __restrict__ w0, const float* __restrict__ w1,
    const float* __restrict__ w2)
{
    int idx = blockIdx.x*256 + threadIdx.x;
    if (idx >= CW_TOT) return;
    const float* src; int s;
    if (idx < CW_N0){ src = w0; s = idx; }
    else if (idx < CW_N1){ src = w1; s = idx - CW_N0; }
    else { src = w2; s = idx - CW_N1; }
    float4 v = __ldg(reinterpret_cast<const float4*>(src) + s);
    __nv_bfloat16 h0,h1,h2,h3,l0,l1,l2,l3;
    split_bf(v.x,h0,l0); split_bf(v.y,h1,l1); split_bf(v.z,h2,l2); split_bf(v.w,h3,l3);
    reinterpret_cast<uint2*>(g_Wh)[idx] = make_uint2(pack_bf2(h0,h1), pack_bf2(h2,h3));
    reinterpret_cast<uint2*>(g_Wl)[idx] = make_uint2(pack_bf2(l0,l1), pack_bf2(l2,l3));
}

// ---------------- split fp32 -> bf16 hi/lo (obs) ----------------------------
__global__ void __launch_bounds__(256) conv_split_kernel(
    const float* __restrict__ x, __nv_bfloat16* __restrict__ hi,
    __nv_bfloat16* __restrict__ lo, size_t n4)
{
    size_t i = (size_t)blockIdx.x*256 + threadIdx.x;
    size_t stride = (size_t)gridDim.x*256;
    for (; i < n4; i += stride){
        float4 v = __ldg(reinterpret_cast<const float4*>(x) + i);
        __nv_bfloat16 h0,h1,h2,h3,l0,l1,l2,l3;
        split_bf(v.x,h0,l0); split_bf(v.y,h1,l1); split_bf(v.z,h2,l2); split_bf(v.w,h3,l3);
        reinterpret_cast<uint2*>(hi)[i] = make_uint2(pack_bf2(h0,h1), pack_bf2(h2,h3));
        reinterpret_cast<uint2*>(lo)[i] = make_uint2(pack_bf2(l0,l1), pack_bf2(l2,l3));
    }
}

// ---------------- bf16 tensor-core GEMM: C = A @ B^T + bias -----------------
// CTA tile 128x64, warp tile 32x32 (8 warps), 2-stage 48KB pipeline.
// 96.3KB smem + <=128 regs -> 2 CTAs/SM (4 warps/SMSP) to hide bubbles.
#define STG2_B 49152                     // Ah 16K | Al 16K | Bh 8K | Bl 8K
#define GEMM_SMEM4 (2*STG2_B + 256)      // 98560

__global__ void __launch_bounds__(256, 2) gemm_bf16_bias(
    const __nv_bfloat16* __restrict__ Ah, const __nv_bfloat16* __restrict__ Al,
    const __nv_bfloat16* __restrict__ Bh, const __nv_bfloat16* __restrict__ Bl,
    const float* __restrict__ bias, float* __restrict__ C, int N, int K)
{
    extern __shared__ char gsm[];
    uint32_t sb = smem_u32(gsm);
    float* biasS = reinterpret_cast<float*>(gsm + 2*STG2_B);

    int tid = threadIdx.x;
    int lane = tid & 31, wid = tid >> 5;
    int wm = wid & 3, wn = wid >> 2;       // 4 m-groups x 2 n-groups
    int n0 = blockIdx.x * 64, m0 = blockIdx.y * 128;

    if (tid < 64) biasS[tid] = bias[n0 + tid];

    float acc[2][4][4];
#pragma unroll
    for (int mt=0; mt<2; mt++)
#pragma unroll
        for (int nt=0; nt<4; nt++)
#pragma unroll
            for (int q=0; q<4; q++) acc[mt][nt][q] = 0.f;

    const int tot = K >> 6;

    auto issue = [&](int c){
        uint32_t base = sb + (uint32_t)(c & 1)*STG2_B;
        int kk = c << 6;
#pragma unroll
        for (int i = 0; i < 12; i++){       // 384 rows x 8 chunks / 256 thr
            int idx = i*256 + tid;
            int chunk = idx >> 3, cc = idx & 7;
            const __nv_bfloat16* sp; int row; int lr; uint32_t tBase;
            if (chunk < 128){ sp = Ah; lr = chunk;       row = m0 + lr; tBase = base; }
            else if (chunk < 256){ sp = Al; lr = chunk-128; row = m0 + lr; tBase = base + 16384; }
            else if (chunk < 320){ sp = Bh; lr = chunk-256; row = n0 + lr; tBase = base + 32768; }
            else { sp = Bl; lr = chunk-320; row = n0 + lr; tBase = base + 40960; }
            uint32_t so = (uint32_t)(lr*128 + cc*16);
            so ^= (so >> 3) & 0x70;
            const void* g = sp + (size_t)row*K + kk + cc*8;
            asm volatile("cp.async.cg.shared.global [%0], [%1], 16;"
                         :: "r"(tBase + so), "l"(g));
        }
        asm volatile("cp.async.commit_group;");
    };

    issue(0);

    int mat = lane >> 3;
    int rowp = ((mat & 2) << 2) + (lane & 7);
    int khalf = (mat & 1) << 4;

    for (int c = 0; c < tot; c++){
        if (c + 1 < tot){
            issue(c + 1);
            asm volatile("cp.async.wait_group 1;");
        } else {
            asm volatile("cp.async.wait_group 0;");
        }
        __syncthreads();
        uint32_t base = sb + (uint32_t)(c & 1)*STG2_B;
        uint32_t aHB = base, aLB = base + 16384;
        uint32_t bHB = base + 32768, bLB = base + 40960;

#pragma unroll
        for (int ks = 0; ks < 4; ks++){
            uint32_t ah[2][4], al[2][4], bh[4][2], bl[4][2];
#pragma unroll
            for (int mt = 0; mt < 2; mt++){
                uint32_t off = (uint32_t)((wm*32 + mt*16 + (lane & 15))*128
                              + ks*32 + ((lane >> 4) << 4));
                off ^= (off >> 3) & 0x70;
                asm volatile("ldmatrix.sync.aligned.m8n8.x4.shared.b16 "
                    "{%0,%1,%2,%3}, [%4];"
                    : "=r"(ah[mt][0]),"=r"(ah[mt][1]),"=r"(ah[mt][2]),"=r"(ah[mt][3])
                    : "r"(aHB + off));
                asm volatile("ldmatrix.sync.aligned.m8n8.x4.shared.b16 "
                    "{%0,%1,%2,%3}, [%4];"
                    : "=r"(al[mt][0]),"=r"(al[mt][1]),"=r"(al[mt][2]),"=r"(al[mt][3])
                    : "r"(aLB + off));
            }
#pragma unroll
            for (int ntp = 0; ntp < 2; ntp++){
                uint32_t off = (uint32_t)((wn*32 + ntp*16 + rowp)*128
                              + ks*32 + khalf);
                off ^= (off >> 3) & 0x70;
                asm volatile("ldmatrix.sync.aligned.m8n8.x4.shared.b16 "
                    "{%0,%1,%2,%3}, [%4];"
                    : "=r"(bh[ntp*2][0]),"=r"(bh[ntp*2][1]),
                      "=r"(bh[ntp*2+1][0]),"=r"(bh[ntp*2+1][1])
                    : "r"(bHB + off));
                asm volatile("ldmatrix.sync.aligned.m8n8.x4.shared.b16 "
                    "{%0,%1,%2,%3}, [%4];"
                    : "=r"(bl[ntp*2][0]),"=r"(bl[ntp*2][1]),
                      "=r"(bl[ntp*2+1][0]),"=r"(bl[ntp*2+1][1])
                    : "r"(bLB + off));
            }
#define MMA16(AV, BV, mt, nt) \
    asm volatile("mma.sync.aligned.m16n8k16.row.col.f32.bf16.bf16.f32 " \
        "{%0,%1,%2,%3}, {%4,%5,%6,%7}, {%8,%9}, {%0,%1,%2,%3};" \
        : "+f"(acc[mt][nt][0]), "+f"(acc[mt][nt][1]), \
          "+f"(acc[mt][nt][2]), "+f"(acc[mt][nt][3]) \
        : "r"(AV[mt][0]),"r"(AV[mt][1]),"r"(AV[mt][2]),"r"(AV[mt][3]), \
          "r"(BV[nt][0]),"r"(BV[nt][1]));
#pragma unroll
            for (int mt = 0; mt < 2; mt++)
#pragma unroll
                for (int nt = 0; nt < 4; nt++){
                    MMA16(ah, bh, mt, nt);
                    MMA16(al, bh, mt, nt);
                    MMA16(ah, bl, mt, nt);
                }
#undef MMA16
        }
        __syncthreads();
    }

#pragma unroll
    for (int mt = 0; mt < 2; mt++){
        int r0 = m0 + wm*32 + mt*16 + (lane >> 2);
#pragma unroll
        for (int nt = 0; nt < 4; nt++){
            int nl = wn*32 + nt*8 + (lane & 3)*2;
            float bx = biasS[nl], by = biasS[nl+1];
            float2 v0 = make_float2(acc[mt][nt][0] + bx, acc[mt][nt][1] + by);
            float2 v1 = make_float2(acc[mt][nt][2] + bx, acc[mt][nt][3] + by);
            *reinterpret_cast<float2*>(&C[(size_t)r0*N + n0 + nl]) = v0;
            *reinterpret_cast<float2*>(&C[(size_t)(r0+8)*N + n0 + nl]) = v1;
        }
    }
}

// ---------------- LayerNorm + ReLU in place (fp32) --------------------------
__global__ void __launch_bounds__(128) ln_relu_kernel(
    float* __restrict__ X, const float* __restrict__ gamma,
    const float* __restrict__ beta)
{
    size_t row = blockIdx.x;
    float* x = X + row*Hh;
    int tid = threadIdx.x;
    float4 v = *reinterpret_cast<float4*>(&x[tid*4]);
    float s = v.x+v.y+v.z+v.w;
    float q = v.x*v.x + v.y*v.y + v.z*v.z + v.w*v.w;
#pragma unroll
    for (int o=16;o>0;o>>=1){
        s += __shfl_xor_sync(0xffffffffu, s, o);
        q += __shfl_xor_sync(0xffffffffu, q, o);
    }
    __shared__ float ss[4], qq[4];
    if ((tid & 31) == 0){ ss[tid>>5] = s; qq[tid>>5] = q; }
    __syncthreads();
    s = ss[0]+ss[1]+ss[2]+ss[3];
    q = qq[0]+qq[1]+qq[2]+qq[3];
    float mu  = s * (1.f/Hh);
    float var = q * (1.f/Hh) - mu*mu;
    float inv = rsqrtf(var + 1e-5f);
    float4 g4 = *reinterpret_cast<const float4*>(&gamma[tid*4]);
    float4 b4 = *reinterpret_cast<const float4*>(&beta[tid*4]);
    v.x = fmaxf((v.x-mu)*inv*g4.x + b4.x, 0.f);
    v.y = fmaxf((v.y-mu)*inv*g4.y + b4.y, 0.f);
    v.z = fmaxf((v.z-mu)*inv*g4.z + b4.z, 0.f);
    v.w = fmaxf((v.w-mu)*inv*g4.w + b4.w, 0.f);
    *reinterpret_cast<float4*>(&x[tid*4]) = v;
}

// ---------------- LayerNorm + ReLU -> bf16 hi/lo split ----------------------
__global__ void __launch_bounds__(128) ln_relu_conv_kernel(
    const float* __restrict__ X, const float* __restrict__ gamma,
    const float* __restrict__ beta,
    __nv_bfloat16* __restrict__ oh, __nv_bfloat16* __restrict__ ol)
{
    size_t row = blockIdx.x;
    const float* x = X + row*Hh;
    int tid = threadIdx.x;
    float4 v = *reinterpret_cast<const float4*>(&x[tid*4]);
    float s = v.x+v.y+v.z+v.w;
    float q = v.x*v.x + v.y*v.y + v.z*v.z + v.w*v.w;
#pragma unroll
    for (int o=16;o>0;o>>=1){
        s += __shfl_xor_sync(0xffffffffu, s, o);
        q += __shfl_xor_sync(0xffffffffu, q, o);
    }
    __shared__ float ss[4], qq[4];
    if ((tid & 31) == 0){ ss[tid>>5] = s; qq[tid>>5] = q; }
    __syncthreads();
    s = ss[0]+ss[1]+ss[2]+ss[3];
    q = qq[0]+qq[1]+qq[2]+qq[3];
    float mu  = s * (1.f/Hh);
    float var = q * (1.f/Hh) - mu*mu;
    float inv = rsqrtf(var + 1e-5f);
    float4 g4 = *reinterpret_cast<const float4*>(&gamma[tid*4]);
    float4 b4 = *reinterpret_cast<const float4*>(&beta[tid*4]);
    v.x = fmaxf((v.x-mu)*inv*g4.x + b4.x, 0.f);
    v.y = fmaxf((v.y-mu)*inv*g4.y + b4.y, 0.f);
    v.z = fmaxf((v.z-mu)*inv*g4.z + b4.z, 0.f);
    v.w = fmaxf((v.w-mu)*inv*g4.w + b4.w, 0.f);
    __nv_bfloat16 h0,h1,h2,h3,l0,l1,l2,l3;
    split_bf(v.x,h0,l0); split_bf(v.y,h1,l1); split_bf(v.z,h2,l2); split_bf(v.w,h3,l3);
    size_t i = row*128 + tid;
    reinterpret_cast<uint2*>(oh)[i] = make_uint2(pack_bf2(h0,h1), pack_bf2(h2,h3));
    reinterpret_cast<uint2*>(ol)[i] = make_uint2(pack_bf2(l0,l1), pack_bf2(l2,l3));
}

// ---------------- persistent GRU scan: split-bf16 mma ------------------------
// h state lives directly in the outs arrays (oh/ol): step t reads row
// b*Tt+(t-1) (or the initial-hidden buffer at t=0) and writes row b*Tt+t.
#define SW_WH 0
#define SW_WL 49152
#define SW_AH 98304
#define SW_AL 163840
#define SW_MS 229376
#define SC_SMEM (229376 + 256)

__global__ void __launch_bounds__(256) gru_scan_mma(
    const float* __restrict__ gi,        // [B*T][3H] (includes bih)
    const float* __restrict__ whh,       // [3H][H]
    const float* __restrict__ bhh,       // [3H]
    const unsigned* __restrict__ dones,  // [B][T] 4-byte words
    const float* __restrict__ hidden,    // [B][H] fp32 h_0
    __nv_bfloat16* __restrict__ oh,      // [B][T][H] bf16 hi (state + outs)
    __nv_bfloat16* __restrict__ ol,
    float* __restrict__ hfin)            // [B][H] fp32 -> d_out head
{
    extern __shared__ char ssm[];
    uint32_t sb = smem_u32(ssm);
    float* Ms = reinterpret_cast<float*>(ssm + SW_MS);

    int tid = threadIdx.x;
    int lane = tid & 31, wid = tid >> 5;
    int mt = wid & 3, cb = wid >> 2;
    int bt = blockIdx.x >> 5, jt = blockIdx.x & 31;
    int b0 = bt*64, j0 = jt*16;

    // load Whh slice (48 rows x 512 k) into smem as bf16 hi/lo, swizzled
    for (int idx = tid; idx < 48*512; idx += 256){
        int rr = idx >> 9;          // 0..47 = g*16 + jc
        int k  = idx & 511;
        int g = rr >> 4, jc = rr & 15;
        int cbw = jc >> 3, rw = jc & 7;
        float w = whh[(size_t)(g*Hh + j0 + jc)*Hh + k];
        __nv_bfloat16 h, l; split_bf(w, h, l);
        int kc = k >> 6, kk = k & 63;
        uint32_t off = (uint32_t)((g*2+cbw)*8192 + kc*1024 + rw*128 + kk*2);
        uint32_t sw = off ^ ((off >> 3) & 0x70);
        *reinterpret_cast<__nv_bfloat16*>(ssm + SW_WH + sw) = h;
        *reinterpret_cast<__nv_bfloat16*>(ssm + SW_WL + sw) = l;
    }

    int r0l = lane >> 2;                 // 0..7
    int mr0 = mt*16 + r0l, mr1 = mr0 + 8;
    int gb0 = b0 + mr0,   gb1 = b0 + mr1;
    int jcol = j0 + cb*8 + (lane & 3)*2;

    float2 bhr = *reinterpret_cast<const float2*>(bhh + jcol);
    float2 bhz = *reinterpret_cast<const float2*>(bhh + Hh + jcol);
    float2 bhn = *reinterpret_cast<const float2*>(bhh + 2*Hh + jcol);

    float2 hp0 = *reinterpret_cast<const float2*>(hidden + (size_t)gb0*Hh + jcol);
    float2 hp1 = *reinterpret_cast<const float2*>(hidden + (size_t)gb1*Hh + jcol);

    __syncthreads();

    int l8 = lane & 15;
    uint32_t bRow4 = (uint32_t)((lane & 7)*128 + ((lane >> 3) << 4));
    uint32_t aRow  = (uint32_t)((mt*16 + l8)*128 + ((lane >> 4) << 4));

    for (int t = 0; t < Tt; t++){
        const __nv_bfloat16* baseH;
        const __nv_bfloat16* baseL;
        size_t rstride;
        if (t == 0){ baseH = g_hbh; baseL = g_hbl; rstride = Hh; }
        else { baseH = oh + (size_t)(t-1)*Hh; baseL = ol + (size_t)(t-1)*Hh;
               rstride = (size_t)Tt*Hh; }

        if (tid < 64)
            Ms[tid] = dones[(size_t)(b0+tid)*Tt + t] ? 0.f : 1.f;

        // stream h tiles in 4 pipelined groups (2 k-chunks each)
#pragma unroll
        for (int grp = 0; grp < 4; grp++){
#pragma unroll
            for (int i = 0; i < 4; i++){
                int idx = grp*1024 + i*256 + tid;
                int kc = idx >> 9, r = (idx >> 3) & 63, cc = idx & 7;
                uint32_t off = (uint32_t)(kc*8192 + r*128 + cc*16);
                off ^= (off >> 3) & 0x70;
                const void* gh = baseH + (size_t)(b0+r)*rstride + kc*64 + cc*8;
                asm volatile("cp.async.cg.shared.global [%0], [%1], 16;"
                             :: "r"(sb + SW_AH + off), "l"(gh));
                const void* gl = baseL + (size_t)(b0+r)*rstride + kc*64 + cc*8;
                asm volatile("cp.async.cg.shared.global [%0], [%1], 16;"
                             :: "r"(sb + SW_AL + off), "l"(gl));
            }
            asm volatile("cp.async.commit_group;");
        }

        // gi prefetch (latency hides under cp.async wait)
        const float* gp0 = gi + ((size_t)gb0*Tt + t)*H3 + jcol;
        const float* gp1 = gi + ((size_t)gb1*Tt + t)*H3 + jcol;
        float2 gr0 = __ldg(reinterpret_cast<const float2*>(gp0));
        float2 gz0 = __ldg(reinterpret_cast<const float2*>(gp0 + Hh));
        float2 gn0 = __ldg(reinterpret_cast<const float2*>(gp0 + 2*Hh));
        float2 gr1 = __ldg(reinterpret_cast<const float2*>(gp1));
        float2 gz1 = __ldg(reinterpret_cast<const float2*>(gp1 + Hh));
        float2 gn1 = __ldg(reinterpret_cast<const float2*>(gp1 + 2*Hh));

        float acc[3][4];
#pragma unroll
        for (int g=0; g<3; g++)
#pragma unroll
            for (int q=0; q<4; q++) acc[g][q] = 0.f;

        float m0f = 1.f, m1f = 1.f;
        uint32_t am0 = 0xFFFFFFFFu, am1m = 0xFFFFFFFFu;

        auto mma2 = [&](int kc0){
#pragma unroll
            for (int kcl = 0; kcl < 2; kcl++){
                int kc = kc0 + kcl;
#pragma unroll
                for (int ksp = 0; ksp < 2; ksp++){
                    uint32_t bh4[3][4], bl4[3][4];
#pragma unroll
                    for (int g = 0; g < 3; g++){
                        uint32_t boff = (uint32_t)((g*2+cb)*8192 + kc*1024 + ksp*64) + bRow4;
                        boff ^= (boff >> 3) & 0x70;
                        asm volatile("ldmatrix.sync.aligned.m8n8.x4.shared.b16 "
                            "{%0,%1,%2,%3}, [%4];"
                            : "=r"(bh4[g][0]),"=r"(bh4[g][1]),
                              "=r"(bh4[g][2]),"=r"(bh4[g][3])
                            : "r"(sb + SW_WH + boff));
                        asm volatile("ldmatrix.sync.aligned.m8n8.x4.shared.b16 "
                            "{%0,%1,%2,%3}, [%4];"
                            : "=r"(bl4[g][0]),"=r"(bl4[g][1]),
                              "=r"(bl4[g][2]),"=r"(bl4[g][3])
                            : "r"(sb + SW_WL + boff));
                    }
#pragma unroll
                    for (int ksi = 0; ksi < 2; ksi++){
                        uint32_t aoff = (uint32_t)(kc*8192 + (ksp*2+ksi)*32) + aRow;
                        aoff ^= (aoff >> 3) & 0x70;
                        uint32_t ah[4], al[4];
                        asm volatile("ldmatrix.sync.aligned.m8n8.x4.shared.b16 "
                            "{%0,%1,%2,%3}, [%4];"
                            : "=r"(ah[0]),"=r"(ah[1]),"=r"(ah[2]),"=r"(ah[3])
                            : "r"(sb + SW_AH + aoff));
                        asm volatile("ldmatrix.sync.aligned.m8n8.x4.shared.b16 "
                            "{%0,%1,%2,%3}, [%4];"
                            : "=r"(al[0]),"=r"(al[1]),"=r"(al[2]),"=r"(al[3])
                            : "r"(sb + SW_AL + aoff));
                        ah[0] &= am0; ah[2] &= am0; ah[1] &= am1m; ah[3] &= am1m;
                        al[0] &= am0; al[2] &= am0; al[1] &= am1m; al[3] &= am1m;
#define MMA1(AV, B0, B1, g) \
    asm volatile("mma.sync.aligned.m16n8k16.row.col.f32.bf16.bf16.f32 " \
        "{%0,%1,%2,%3}, {%4,%5,%6,%7}, {%8,%9}, {%0,%1,%2,%3};" \
        : "+f"(acc[g][0]), "+f"(acc[g][1]), "+f"(acc[g][2]), "+f"(acc[g][3]) \
        : "r"(AV[0]),"r"(AV[1]),"r"(AV[2]),"r"(AV[3]), "r"(B0),"r"(B1));
#pragma unroll
                        for (int g = 0; g < 3; g++)
                            MMA1(ah, bh4[g][ksi*2], bh4[g][ksi*2+1], g);
#pragma unroll
                        for (int g = 0; g < 3; g++)
                            MMA1(al, bh4[g][ksi*2], bh4[g][ksi*2+1], g);
#pragma unroll
                        for (int g = 0; g < 3; g++)
                            MMA1(ah, bl4[g][ksi*2], bl4[g][ksi*2+1], g);
#undef MMA1
                    }
                }
            }
        };

        asm volatile("cp.async.wait_group 3;");
        __syncthreads();
        m0f = Ms[mr0]; m1f = Ms[mr1];
        am0  = (m0f != 0.f) ? 0xFFFFFFFFu : 0u;
        am1m = (m1f != 0.f) ? 0xFFFFFFFFu : 0u;
        mma2(0);
        asm volatile("cp.async.wait_group 2;");
        __syncthreads();
        mma2(2);
        asm volatile("cp.async.wait_group 1;");
        __syncthreads();
        mma2(4);
        asm volatile("cp.async.wait_group 0;");
        __syncthreads();
        mma2(6);

        // epilogue (thread-local)
        hp0.x *= m0f; hp0.y *= m0f; hp1.x *= m1f; hp1.y *= m1f;
        float rg0x = sigmoidf_(gr0.x + acc[0][0] + bhr.x);
        float rg0y = sigmoidf_(gr0.y + acc[0][1] + bhr.y);
        float z0x  = sigmoidf_(gz0.x + acc[1][0] + bhz.x);
        float z0y  = sigmoidf_(gz0.y + acc[1][1] + bhz.y);
        float n0x  = tanhf_fast(gn0.x + rg0x*(acc[2][0] + bhn.x));
        float n0y  = tanhf_fast(gn0.y + rg0y*(acc[2][1] + bhn.y));
        hp0.x = (1.f - z0x)*n0x + z0x*hp0.x;
        hp0.y = (1.f - z0y)*n0y + z0y*hp0.y;
        float rg1x = sigmoidf_(gr1.x + acc[0][2] + bhr.x);
        float rg1y = sigmoidf_(gr1.y + acc[0][3] + bhr.y);
        float z1x  = sigmoidf_(gz1.x + acc[1][2] + bhz.x);
        float z1y  = sigmoidf_(gz1.y + acc[1][3] + bhz.y);
        float n1x  = tanhf_fast(gn1.x + rg1x*(acc[2][2] + bhn.x));
        float n1y  = tanhf_fast(gn1.y + rg1y*(acc[2][3] + bhn.y));
        hp1.x = (1.f - z1x)*n1x + z1x*hp1.x;
        hp1.y = (1.f - z1y)*n1y + z1y*hp1.y;

        __nv_bfloat16 hx, hy, lx, ly;
        split_bf(hp0.x, hx, lx); split_bf(hp0.y, hy, ly);
        uint32_t ph0 = pack_bf2(hx, hy), pl0 = pack_bf2(lx, ly);
        split_bf(hp1.x, hx, lx); split_bf(hp1.y, hy, ly);
        uint32_t ph1 = pack_bf2(hx, hy), pl1 = pack_bf2(lx, ly);

        size_t oi0 = (((size_t)gb0*Tt + t)*Hh + jcol) >> 1;
        size_t oi1 = (((size_t)gb1*Tt + t)*Hh + jcol) >> 1;
        reinterpret_cast<uint32_t*>(oh)[oi0] = ph0;
        reinterpret_cast<uint32_t*>(ol)[oi0] = pl0;
        reinterpret_cast<uint32_t*>(oh)[oi1] = ph1;
        reinterpret_cast<uint32_t*>(ol)[oi1] = pl1;
        if (t == Tt-1){
            *reinterpret_cast<float2*>(&hfin[(size_t)gb0*Hh + jcol]) = hp0;
            *reinterpret_cast<float2*>(&hfin[(size_t)gb1*Hh + jcol]) = hp1;
        }

        // per-btile barrier (32 CTAs): release by tid0 after CTA barrier
        __syncthreads();
        if (tid == 0){
            __threadfence();
            unsigned* ctr = &g_bar[bt*Tt + t];
            unsigned a = atomicAdd(ctr, 1u) + 1u;
            if (a < 32u){
                unsigned v;
                do {
                    asm volatile("ld.global.cg.u32 %0, [%1];" : "=r"(v) : "l"(ctr));
                    if (v >= 32u) break;
                    __nanosleep(8);
                } while (true);
            }
            __threadfence();
        }
        __syncthreads();
    }
}

// ---------------- logits: am @ am2_w^T + b, availability mask ---------------
__global__ void __launch_bounds__(256) logits_kernel(
    const float* __restrict__ am, const float* __restrict__ w2,
    const float* __restrict__ b2, const float* __restrict__ avail,
    float* __restrict__ out)
{
    __shared__ float Ws2[Aa*Hh];
    __shared__ float bs[Aa];
    int tid = threadIdx.x;
    for (int idx = tid; idx < Aa*Hh; idx += 256) Ws2[idx] = w2[idx];
    if (tid < Aa) bs[tid] = b2[tid];
    __syncthreads();

    int warp = tid >> 5, lane = tid & 31;
    size_t row = (size_t)blockIdx.x*8 + warp;
    float acc[Aa];
#pragma unroll
    for (int j=0;j<Aa;j++) acc[j] = 0.f;
#pragma unroll 4
    for (int s=0;s<16;s++){
        int k = s*32 + lane;
        float a = am[row*Hh + k];
#pragma unroll
        for (int j=0;j<Aa;j++) acc[j] += a * Ws2[j*Hh + k];
    }
#pragma unroll
    for (int j=0;j<Aa;j++)
#pragma unroll
        for (int o=16;o>0;o>>=1)
            acc[j] += __shfl_xor_sync(0xffffffffu, acc[j], o);
    if (lane == 0){
#pragma unroll
        for (int j=0;j<Aa;j++){
            float av = avail[row*Aa + j];
            out[row*Aa + j] = acc[j] + bs[j] - (1.f - av)*1e10f;
        }
    }
}

// ---------------- host launch ------------------------------------------------
extern "C" void kernel_launch(void* const* d_in, const int* in_sizes, int n_in,
                              void* d_out, int out_size)
{
    const float*    hidden = (const float*)d_in[0];
    const float*    obs    = (const float*)d_in[1];
    const unsigned* dones  = (const unsigned*)d_in[2];
    const float*    avail  = (const float*)d_in[3];
    const float*    in_w   = (const float*)d_in[4];
    const float*    in_b   = (const float*)d_in[5];
    const float*    ln_g   = (const float*)d_in[6];
    const float*    ln_b   = (const float*)d_in[7];
    const float*    wih    = (const float*)d_in[8];
    const float*    whh    = (const float*)d_in[9];
    const float*    bih    = (const float*)d_in[10];
    const float*    bhh    = (const float*)d_in[11];
    const float*    am1_w  = (const float*)d_in[12];
    const float*    am1_b  = (const float*)d_in[13];
    const float*    amln_g = (const float*)d_in[14];
    const float*    amln_b = (const float*)d_in[15];
    const float*    am2_w  = (const float*)d_in[16];
    const float*    am2_b  = (const float*)d_in[17];
    float* out = (float*)d_out;

    void *p_b0, *p_gi, *p_ah, *p_al, *p_wh, *p_wl;
    cudaGetSymbolAddress(&p_b0, g_buf0);
    cudaGetSymbolAddress(&p_gi, g_gi);
    cudaGetSymbolAddress(&p_ah, g_Ah);
    cudaGetSymbolAddress(&p_al, g_Al);
    cudaGetSymbolAddress(&p_wh, g_Wh);
    cudaGetSymbolAddress(&p_wl, g_Wl);
    float* buf0 = (float*)p_b0;
    float* gip  = (float*)p_gi;
    __nv_bfloat16* Ah = (__nv_bfloat16*)p_ah;
    __nv_bfloat16* Al = (__nv_bfloat16*)p_al;
    __nv_bfloat16* Wh = (__nv_bfloat16*)p_wh;
    __nv_bfloat16* Wl = (__nv_bfloat16*)p_wl;

    cudaFuncSetAttribute(gru_scan_mma,
        cudaFuncAttributeMaxDynamicSharedMemorySize, SC_SMEM);
    cudaFuncSetAttribute(gemm_bf16_bias,
        cudaFuncAttributeMaxDynamicSharedMemorySize, GEMM_SMEM4);

    // launch 0: barrier clear + hidden split
    init_misc_kernel<<<128, 256>>>(hidden);
    // launch 1: all weight splits
    conv_w3_kernel<<<(CW_TOT+255)/256, 256>>>(in_w, wih, am1_w);
    // launch 2: obs split
    conv_split_kernel<<<16384, 256>>>(obs, Ah, Al, (size_t)BT*Hh/4);

    dim3 gH(Hh/64, BT/128);        // (8, 1024)
    dim3 gG(H3/64, BT/128);        // (24, 1024)

    // pre-RNN MLP x3 (launch 5 = gemm #2 -> ncu capture)
    gemm_bf16_bias<<<gH, 256, GEMM_SMEM4>>>(Ah, Al, Wh + OFF_INW, Wl + OFF_INW,
                                            in_b, buf0, Hh, Hh);
    ln_relu_conv_kernel<<<BT, 128>>>(buf0, ln_g, ln_b, Ah, Al);
    gemm_bf16_bias<<<gH, 256, GEMM_SMEM4>>>(Ah, Al, Wh + OFF_INW + Hh*Hh,
                                            Wl + OFF_INW + Hh*Hh,
                                            in_b + Hh, buf0, Hh, Hh);
    ln_relu_conv_kernel<<<BT, 128>>>(buf0, ln_g + Hh, ln_b + Hh, Ah, Al);
    gemm_bf16_bias<<<gH, 256, GEMM_SMEM4>>>(Ah, Al, Wh + OFF_INW + 2*Hh*Hh,
                                            Wl + OFF_INW + 2*Hh*Hh,
                                            in_b + 2*Hh, buf0, Hh, Hh);
    ln_relu_conv_kernel<<<BT, 128>>>(buf0, ln_g + 2*Hh, ln_b + 2*Hh, Ah, Al);

    // GRU input projection for all timesteps at once
    gemm_bf16_bias<<<gG, 256, GEMM_SMEM4>>>(Ah, Al, Wh + OFF_WIH, Wl + OFF_WIH,
                                            bih, gip, H3, Hh);

    // sequential GRU scan (persistent; h state lives in Ah/Al = outs)
    gru_scan_mma<<<128, 256, SC_SMEM>>>(gip, whh, bhh, dones, hidden,
                                        Ah, Al, out);

    // actor head: Linear -> LN -> ReLU -> logits
    gemm_bf16_bias<<<gH, 256, GEMM_SMEM4>>>(Ah, Al, Wh + OFF_AM1, Wl + OFF_AM1,
                                            am1_b, buf0, Hh, Hh);
    ln_relu_kernel<<<BT, 128>>>(buf0, amln_g, amln_b);
    logits_kernel<<<BT/8, 256>>>(buf0, am2_w, am2_b, avail, out + (size_t)Bb*Hh);
}